// round 12
// baseline (speedup 1.0000x reference)
#include <cuda_runtime.h>
#include <cuda_fp16.h>
#include <math.h>
#include <stdint.h>

#define NNODES 3070
#define NFEAT 128
#define NOUT 64
#define HS 50
#define HSP 52           // fp32 pre row: 52 floats
#define USTR 64          // fp16 u row: 64 halves = 128B (one cache line)
#define NEDGES 49120
#define NB 128
#define NROWS (NB * NNODES)
#define PREP_CTAS 192
#define PREP_GTH (PREP_CTAS * 256)

// ---------------- device scratch (static, no allocations) ----------------
__device__ int   g_present[NNODES];   // idempotent marks; never re-zeroed
__device__ int   g_rank[NNODES];
__device__ float g_deg[NNODES];
__device__ float g_dinv[NNODES];
__device__ int   g_counts[NNODES];
__device__ int   g_csrptr[NNODES + 1];
__device__ int   g_cursor[NNODES];
__device__ int   g_esrc[NEDGES];
__device__ int   g_edst[NEDGES];
__device__ __align__(8) float2 g_epack[NEDGES];  // (norm_w, src*USTR as int bits)
// B fragments in mma order: [s(16)][jp(4)][lane(32)][slot(4)] = 32KB
__device__ __align__(16) float g_Bfrag[16 * 4 * 32 * 4];
__device__ __align__(16) float g_cvec[HSP];
__device__ __align__(256) __half g_u[(size_t)NROWS * USTR];
// padded by one batch-row so RNN prefetch can run unconditionally
__device__ __align__(16) float g_pre[(size_t)(NROWS + NNODES) * HSP];
// grid barrier state (generation-based, self-resetting -> replay-safe)
__device__ volatile int g_bar_gen;
__device__ int g_bar_cnt;

__device__ __forceinline__ void gridbar() {
    __syncthreads();
    if (threadIdx.x == 0) {
        int gen = g_bar_gen;
        __threadfence();
        if (atomicAdd(&g_bar_cnt, 1) == PREP_CTAS - 1) {
            g_bar_cnt = 0;
            __threadfence();
            g_bar_gen = gen + 1;
        } else {
            while (g_bar_gen == gen) __nanosleep(64);
        }
        __threadfence();
    }
    __syncthreads();
}

__device__ __forceinline__ uint32_t to_tf32(float f) {
    uint32_t r;
    asm("cvt.rna.tf32.f32 %0, %1;" : "=r"(r) : "f"(f));
    return r;
}
__device__ __forceinline__ void mma_tf32(float* d, const uint32_t* a,
                                         uint32_t b0, uint32_t b1) {
    asm volatile(
        "mma.sync.aligned.m16n8k8.row.col.f32.tf32.tf32.f32 "
        "{%0,%1,%2,%3}, {%4,%5,%6,%7}, {%8,%9}, {%0,%1,%2,%3};"
        : "+f"(d[0]), "+f"(d[1]), "+f"(d[2]), "+f"(d[3])
        : "r"(a[0]), "r"(a[1]), "r"(a[2]), "r"(a[3]), "r"(b0), "r"(b1));
}
// accurate fast tanh: ex2/rcp approx are ~2^-23 rel err -> ~1e-6 overall
__device__ __forceinline__ float fast_tanh(float x) {
    float e;
    asm("ex2.approx.f32 %0, %1;" : "=f"(e) : "f"(x * 2.8853900817779268f));
    float r;
    asm("rcp.approx.f32 %0, %1;" : "=f"(r) : "f"(e + 1.0f));
    return fmaf(-2.0f, r, 1.0f);
}
// packed f32x2 fma (Blackwell FFMA2, base sm_100+ feature)
__device__ __forceinline__ unsigned long long fma2(unsigned long long a,
                                                   unsigned long long b,
                                                   unsigned long long c) {
    unsigned long long d;
    asm("fma.rn.f32x2 %0, %1, %2, %3;" : "=l"(d) : "l"(a), "l"(b), "l"(c));
    return d;
}
__device__ __forceinline__ unsigned long long pk2(float x, float y) {
    unsigned long long r;
    asm("mov.b64 %0, {%1, %2};" : "=l"(r) : "f"(x), "f"(y));
    return r;
}
__device__ __forceinline__ float2 upk2(unsigned long long v) {
    float2 r;
    asm("mov.b64 {%0, %1}, %2;" : "=f"(r.x), "=f"(r.y) : "l"(v));
    return r;
}

__device__ __forceinline__ int load_eid(const void* eidx, int i, int is64) {
    if (is64) return (int)((const long long*)eidx)[i];
    return ((const int*)eidx)[i];
}

// ---------------- prep: ALL graph preprocessing, one grid-resident kernel -------
__global__ void __launch_bounds__(256) k_prep(const void* eidx,
                                              const float* __restrict__ ew,
                                              const float* __restrict__ W,
                                              const float* __restrict__ b,
                                              const float* __restrict__ W_ih,
                                              const float* __restrict__ b_ih) {
    __shared__ int s_is64;
    __shared__ int s1[256], s2[256];
    int t = threadIdx.x;
    int i = blockIdx.x * 256 + t;
    // fast parallel dtype detect: int64 ids < 3070 => odd 32-bit words zero
    if (t < 32) {
        int val = (t < 8) ? ((const int*)eidx)[2 * t + 1] : 0;
        int any = __any_sync(0xffffffffu, val != 0);
        if (t == 0) s_is64 = !any;
    }
    __syncthreads();
    int is64 = s_is64;
    // ---- phase A: mark + init + B fragments + cvec ----
    for (int j = i; j < 2 * NEDGES; j += PREP_GTH)
        g_present[load_eid(eidx, j, is64)] = 1;
    if (i < NNODES) { g_deg[i] = 1.0f; g_counts[i] = 0; }
    if (i < 128 * 64) {
        int k = i >> 6, c = i & 63;
        float v = 0.f;
        if (c < HS) {
            float s = 0.f;
            #pragma unroll 8
            for (int o = 0; o < NOUT; o++) s += W[k * NOUT + o] * W_ih[c * NOUT + o];
            v = __uint_as_float(to_tf32(s));
        }
        int t16 = k >> 4, j = k & 15, q = j >> 2, r = j & 3;
        int sct = 2 * t16 + (r >> 1);
        int bidx = r & 1;
        int klo = q;
        int jcol = c >> 3, nr = c & 7, jp = jcol >> 1, jodd = jcol & 1;
        int lane = nr * 4 + klo;
        g_Bfrag[(((sct * 4 + jp) * 32 + lane) << 2) + jodd * 2 + bidx] = v;
    }
    int ci = i - 128 * 64;
    if (ci >= 0 && ci < HS) {
        float s = b_ih[ci];
        #pragma unroll 8
        for (int o = 0; o < NOUT; o++) s += b[o] * W_ih[ci * NOUT + o];
        g_cvec[ci] = s;
    }
    if (ci == HS) { g_cvec[50] = 0.f; g_cvec[51] = 0.f; }
    gridbar();
    // ---- phase B: scan present -> rank (CTA 0) ----
    if (blockIdx.x == 0) {
        int base = t * 12;
        int c[12];
        int sum = 0;
        #pragma unroll
        for (int k = 0; k < 12; k++) {
            int idx = base + k;
            int v = (idx < NNODES) ? g_present[idx] : 0;
            c[k] = sum;
            sum += v;
        }
        s1[t] = sum;
        __syncthreads();
        int* src = s1; int* dst = s2;
        for (int off = 1; off < 256; off <<= 1) {
            int val = src[t];
            if (t >= off) val += src[t - off];
            dst[t] = val;
            __syncthreads();
            int* tmp = src; src = dst; dst = tmp;
        }
        int excl = src[t] - sum;
        #pragma unroll
        for (int k = 0; k < 12; k++) {
            int idx = base + k;
            if (idx < NNODES) g_rank[idx] = excl + c[k];
        }
    }
    gridbar();
    // ---- phase C: remap edges + degree/counts ----
    if (i < NEDGES) {
        int sid = load_eid(eidx, i, is64);
        int did = load_eid(eidx, NEDGES + i, is64);
        int s = g_rank[sid], d = g_rank[did];
        g_esrc[i] = s;
        g_edst[i] = d;
        atomicAdd(&g_deg[d], ew[i]);
        atomicAdd(&g_counts[d], 1);
    }
    gridbar();
    // ---- phase D: scan counts -> csrptr/cursor; dinv (CTA 0) ----
    if (blockIdx.x == 0) {
        int base = t * 12;
        int c[12];
        int sum = 0;
        #pragma unroll
        for (int k = 0; k < 12; k++) {
            int idx = base + k;
            int v = (idx < NNODES) ? g_counts[idx] : 0;
            c[k] = sum;
            sum += v;
        }
        __syncthreads();   // s1/s2 reuse
        s1[t] = sum;
        __syncthreads();
        int* src = s1; int* dst = s2;
        for (int off = 1; off < 256; off <<= 1) {
            int val = src[t];
            if (t >= off) val += src[t - off];
            dst[t] = val;
            __syncthreads();
            int* tmp = src; src = dst; dst = tmp;
        }
        int incl = src[t];
        int excl = incl - sum;
        #pragma unroll
        for (int k = 0; k < 12; k++) {
            int idx = base + k;
            if (idx < NNODES) {
                int e = excl + c[k];
                g_csrptr[idx] = e;
                g_cursor[idx] = e;
                g_dinv[idx] = rsqrtf(g_deg[idx]);
            }
        }
        if (t == 255) g_csrptr[NNODES] = incl;
    }
    gridbar();
    // ---- phase E: fill CSR (packed w, src*USTR) ----
    if (i < NEDGES) {
        int d = g_edst[i], s = g_esrc[i];
        int pos = atomicAdd(&g_cursor[d], 1);
        g_epack[pos] = make_float2(g_dinv[s] * ew[i] * g_dinv[d],
                                   __int_as_float(s * USTR));
    }
}

// ---------------- GEMM: u = x @ M via mma.sync tf32 m16n8k8, fp16 out -----------
__global__ void __launch_bounds__(128) k_gemm(const float* __restrict__ x) {
    __shared__ __align__(16) float4 Bs[16 * 4 * 32];
    int tid = threadIdx.x, wid = tid >> 5, lane = tid & 31;
    {
        const float4* s = (const float4*)g_Bfrag;
        #pragma unroll
        for (int i = 0; i < 16; i++) Bs[tid + 128 * i] = s[tid + 128 * i];
    }
    size_t rowbase = (size_t)blockIdx.x * 128;
    int grp = lane >> 2, qid = lane & 3;
    const float* px = x + (rowbase + wid * 32 + grp) * NFEAT + 4 * qid;
    __syncthreads();

    float d[14][4];
    #pragma unroll
    for (int i = 0; i < 14; i++)
        #pragma unroll
        for (int j = 0; j < 4; j++) d[i][j] = 0.f;

    #pragma unroll
    for (int t = 0; t < 8; t++) {
        float4 v0 = *(const float4*)(px + 16 * t);
        float4 v1 = *(const float4*)(px + 8 * NFEAT + 16 * t);
        float4 v2 = *(const float4*)(px + 16 * NFEAT + 16 * t);
        float4 v3 = *(const float4*)(px + 24 * NFEAT + 16 * t);
        #pragma unroll
        for (int ss = 0; ss < 2; ss++) {
            int s = 2 * t + ss;
            uint32_t am0[4], am1[4];
            if (ss == 0) {
                am0[0] = to_tf32(v0.x); am0[1] = to_tf32(v1.x);
                am0[2] = to_tf32(v0.y); am0[3] = to_tf32(v1.y);
                am1[0] = to_tf32(v2.x); am1[1] = to_tf32(v3.x);
                am1[2] = to_tf32(v2.y); am1[3] = to_tf32(v3.y);
            } else {
                am0[0] = to_tf32(v0.z); am0[1] = to_tf32(v1.z);
                am0[2] = to_tf32(v0.w); am0[3] = to_tf32(v1.w);
                am1[0] = to_tf32(v2.z); am1[1] = to_tf32(v3.z);
                am1[2] = to_tf32(v2.w); am1[3] = to_tf32(v3.w);
            }
            float4 bv[4];
            #pragma unroll
            for (int jp = 0; jp < 4; jp++) bv[jp] = Bs[(s * 4 + jp) * 32 + lane];
            const uint32_t* bu = (const uint32_t*)bv;
            #pragma unroll
            for (int jt = 0; jt < 7; jt++) {
                uint32_t b0 = bu[jt * 2], b1 = bu[jt * 2 + 1];
                mma_tf32(d[jt], am0, b0, b1);
                mma_tf32(d[7 + jt], am1, b0, b1);
            }
        }
    }
    __half2 z2 = __float2half2_rn(0.f);
    #pragma unroll
    for (int mt = 0; mt < 2; mt++) {
        size_t r0 = rowbase + wid * 32 + mt * 16 + grp;
        __half* p0 = g_u + r0 * USTR;
        #pragma unroll
        for (int jt = 0; jt < 7; jt++) {
            int c0 = jt * 8 + 2 * qid;
            __half2 lo, hi;
            if (jt < 6 || qid == 0) {
                lo = __floats2half2_rn(d[mt * 7 + jt][0], d[mt * 7 + jt][1]);
                hi = __floats2half2_rn(d[mt * 7 + jt][2], d[mt * 7 + jt][3]);
            } else { lo = z2; hi = z2; }
            *(__half2*)(p0 + c0) = lo;
            *(__half2*)(p0 + 8 * USTR + c0) = hi;
        }
        int c0 = 56 + 2 * qid;
        *(__half2*)(p0 + c0) = z2;
        *(__half2*)(p0 + 8 * USTR + c0) = z2;
    }
}

// ---------------- dummy: occupies launch slot so spmm lands on ncu -s 5 ---------
__global__ void k_dummy() {}

// ---------------- SpMM: warp per (n,b), n-major; full-warp row gather -----------
// Lane l owns cols {2l, 2l+1}: one 128B line per edge, packed metadata, no shfl.
__global__ void __launch_bounds__(256) k_spmm() {
    int gw = blockIdx.x * 8 + (threadIdx.x >> 5);
    int lane = threadIdx.x & 31;
    int n = gw >> 7;          // 128 batches per node, same n across CTA
    int b = gw & 127;
    const __half* ub = g_u + (size_t)b * (NNODES * USTR) + 2 * lane;
    int e0 = g_csrptr[n], e1 = g_csrptr[n + 1];
    float sx = 0.f, sy = 0.f;
    int e = e0;
    for (; e + 3 < e1; e += 4) {
        float2 m0 = g_epack[e],     m1 = g_epack[e + 1];
        float2 m2 = g_epack[e + 2], m3 = g_epack[e + 3];
        float2 f0 = __half22float2(*(const __half2*)(ub + __float_as_int(m0.y)));
        float2 f1 = __half22float2(*(const __half2*)(ub + __float_as_int(m1.y)));
        float2 f2 = __half22float2(*(const __half2*)(ub + __float_as_int(m2.y)));
        float2 f3 = __half22float2(*(const __half2*)(ub + __float_as_int(m3.y)));
        sx += m0.x * f0.x + m1.x * f1.x + m2.x * f2.x + m3.x * f3.x;
        sy += m0.x * f0.y + m1.x * f1.y + m2.x * f2.y + m3.x * f3.y;
    }
    for (; e < e1; e++) {
        float2 m0 = g_epack[e];
        float2 f0 = __half22float2(*(const __half2*)(ub + __float_as_int(m0.y)));
        sx += m0.x * f0.x;
        sy += m0.x * f0.y;
    }
    if (lane < 25) {
        float dv = g_dinv[n];
        float ws = dv * dv;
        float2 fs = __half22float2(*(const __half2*)(ub + n * USTR));
        float2 cv = *(const float2*)(g_cvec + 2 * lane);
        *(float2*)(g_pre + ((size_t)b * NNODES + n) * HSP + 2 * lane) =
            make_float2(sx + ws * fs.x + cv.x, sy + ws * fs.y + cv.y);
    }
}

// ---------------- RNN: warp per node, FFMA2 packed math, double-buffered h ------
__global__ void __launch_bounds__(256) k_rnn(const float* __restrict__ Whh,
                                             const float* __restrict__ bhh,
                                             const float* __restrict__ h0,
                                             float* __restrict__ out) {
    int w = blockIdx.x * 8 + (threadIdx.x >> 5);
    int lane = threadIdx.x & 31;
    if (w >= NNODES) return;
    __shared__ __align__(16) float hsm[8][2][56];
    float* hc = hsm[threadIdx.x >> 5][0];
    float* hn = hsm[threadIdx.x >> 5][1];
    bool hi = lane < 18;
    int c1 = hi ? 32 + lane : 0;
    // pack W_hh rows into f32x2 pairs (26 per output col; pair 25 = 0)
    unsigned long long w0p[26], w1p[26];
    #pragma unroll
    for (int k = 0; k < 25; k++) {
        w0p[k] = pk2(Whh[lane * HS + 2 * k], Whh[lane * HS + 2 * k + 1]);
        w1p[k] = pk2(Whh[c1 * HS + 2 * k], Whh[c1 * HS + 2 * k + 1]);
    }
    unsigned long long zz = pk2(0.f, 0.f);
    w0p[25] = zz; w1p[25] = zz;
    float b0 = bhh[lane];
    float b1 = bhh[c1];
    hc[lane] = h0[(size_t)w * HS + lane];
    if (hi) hc[32 + lane] = h0[(size_t)w * HS + 32 + lane];
    if (lane == 0) { hc[50] = 0.f; hc[51] = 0.f; hn[50] = 0.f; hn[51] = 0.f; }
    __syncwarp();
    const float* prew = g_pre + (size_t)w * HSP;
    float* outw = out + (size_t)w * HS;
    const size_t pstr = (size_t)NNODES * HSP;
    const size_t ostr = (size_t)NNODES * HS;
    float pa0 = prew[lane];
    float pa1 = hi ? prew[32 + lane] : 0.f;
    for (int t = 0; t < NB; t++) {
        float a0 = pa0 + b0;
        float a1 = pa1 + b1;
        // unconditional prefetch (g_pre padded by one batch-row)
        pa0 = prew[pstr + lane];
        pa1 = hi ? prew[pstr + 32 + lane] : 0.f;
        prew += pstr;
        unsigned long long acc0 = zz, acc1 = zz, acc2 = zz, acc3 = zz;
        #pragma unroll
        for (int kk = 0; kk < 13; kk++) {
            ulonglong2 hp = *(const ulonglong2*)&hc[kk * 4];
            acc0 = fma2(hp.x, w0p[2 * kk], acc0);
            acc1 = fma2(hp.y, w0p[2 * kk + 1], acc1);
            acc2 = fma2(hp.x, w1p[2 * kk], acc2);
            acc3 = fma2(hp.y, w1p[2 * kk + 1], acc3);
        }
        float2 u0 = upk2(acc0), u1 = upk2(acc1);
        float2 u2 = upk2(acc2), u3 = upk2(acc3);
        float t0 = fast_tanh(a0 + (u0.x + u0.y) + (u1.x + u1.y));
        float t1 = fast_tanh(a1 + (u2.x + u2.y) + (u3.x + u3.y));
        hn[lane] = t0;
        if (hi) hn[32 + lane] = t1;
        __syncwarp();
        float* tmp = hc; hc = hn; hn = tmp;
        outw[lane] = t0;
        if (hi) outw[32 + lane] = t1;
        outw += ostr;
    }
}

// ---------------- launch ----------------
extern "C" void kernel_launch(void* const* d_in, const int* in_sizes, int n_in,
                              void* d_out, int out_size) {
    const float* x    = (const float*)d_in[0];
    const void*  eidx = d_in[1];
    const float* ew   = (const float*)d_in[2];
    const float* W    = (const float*)d_in[3];
    const float* b    = (const float*)d_in[4];
    const float* W_ih = (const float*)d_in[5];
    const float* W_hh = (const float*)d_in[6];
    const float* b_ih = (const float*)d_in[7];
    const float* b_hh = (const float*)d_in[8];
    const float* h0   = (const float*)d_in[9];
    float* out = (float*)d_out;

    k_prep<<<PREP_CTAS, 256>>>(eidx, ew, W, b, W_ih, b_ih);  // 0
    k_gemm<<<NNODES, 128>>>(x);                              // 1
    k_dummy<<<1, 32>>>();                                    // 2
    k_spmm<<<(NB * NNODES) / 8, 256>>>();                    // 3  <- profiled
    k_rnn<<<(NNODES + 7) / 8, 256>>>(W_hh, b_hh, h0, out);   // 4
}

// round 13
// speedup vs baseline: 1.1913x; 1.1913x over previous
#include <cuda_runtime.h>
#include <cuda_fp16.h>
#include <math.h>
#include <stdint.h>

#define NNODES 3070
#define NFEAT 128
#define NOUT 64
#define HS 50
#define HSP 52           // fp32 pre row: 52 floats
#define USTR 64          // fp16 u row: 64 halves = 128B (one cache line)
#define NEDGES 49120
#define NB 128
#define NROWS (NB * NNODES)

// ---------------- device scratch (static, no allocations) ----------------
__device__ int   g_is64;
__device__ int   g_present[NNODES];   // idempotent marks; never re-zeroed
__device__ int   g_rank[NNODES];
__device__ float g_deg[NNODES];
__device__ float g_dinv[NNODES];
__device__ int   g_counts[NNODES];
__device__ int   g_csrptr[NNODES + 1];
__device__ int   g_cursor[NNODES];
__device__ int   g_esrc[NEDGES];
__device__ int   g_edst[NEDGES];
__device__ __align__(8) float2 g_epack[NEDGES];  // (norm_w, src*USTR as int bits)
// B fragments in mma order: [s(16)][jp(4)][lane(32)][slot(4)] = 32KB
__device__ __align__(16) float g_Bfrag[16 * 4 * 32 * 4];
__device__ __align__(16) float g_cvec[HSP];
__device__ __align__(256) __half g_u[(size_t)NROWS * USTR];
// padded by TWO batch-rows so RNN prefetch distance 2 is branch-free
__device__ __align__(16) float g_pre[(size_t)(NROWS + 2 * NNODES) * HSP];

__device__ __forceinline__ uint32_t to_tf32(float f) {
    uint32_t r;
    asm("cvt.rna.tf32.f32 %0, %1;" : "=r"(r) : "f"(f));
    return r;
}
__device__ __forceinline__ void mma_tf32(float* d, const uint32_t* a,
                                         uint32_t b0, uint32_t b1) {
    asm volatile(
        "mma.sync.aligned.m16n8k8.row.col.f32.tf32.tf32.f32 "
        "{%0,%1,%2,%3}, {%4,%5,%6,%7}, {%8,%9}, {%0,%1,%2,%3};"
        : "+f"(d[0]), "+f"(d[1]), "+f"(d[2]), "+f"(d[3])
        : "r"(a[0]), "r"(a[1]), "r"(a[2]), "r"(a[3]), "r"(b0), "r"(b1));
}
// accurate fast tanh: ex2/rcp approx are ~2^-23 rel err -> ~1e-6 overall
__device__ __forceinline__ float fast_tanh(float x) {
    float e;
    asm("ex2.approx.f32 %0, %1;" : "=f"(e) : "f"(x * 2.8853900817779268f));
    float r;
    asm("rcp.approx.f32 %0, %1;" : "=f"(r) : "f"(e + 1.0f));
    return fmaf(-2.0f, r, 1.0f);
}
// packed f32x2 fma (Blackwell FFMA2, base sm_100+ feature)
__device__ __forceinline__ unsigned long long fma2(unsigned long long a,
                                                   unsigned long long b,
                                                   unsigned long long c) {
    unsigned long long d;
    asm("fma.rn.f32x2 %0, %1, %2, %3;" : "=l"(d) : "l"(a), "l"(b), "l"(c));
    return d;
}
__device__ __forceinline__ unsigned long long pk2(float x, float y) {
    unsigned long long r;
    asm("mov.b64 %0, {%1, %2};" : "=l"(r) : "f"(x), "f"(y));
    return r;
}
__device__ __forceinline__ float2 upk2(unsigned long long v) {
    float2 r;
    asm("mov.b64 {%0, %1}, %2;" : "=f"(r.x), "=f"(r.y) : "l"(v));
    return r;
}

__device__ __forceinline__ int load_eid(const void* eidx, int i, int is64) {
    if (is64) return (int)((const long long*)eidx)[i];
    return ((const int*)eidx)[i];
}

// ---------------- setup: mark + init + B fragments + cvec -----------------------
__global__ void k_setup(const void* eidx,
                        const float* __restrict__ W, const float* __restrict__ b,
                        const float* __restrict__ W_ih, const float* __restrict__ b_ih) {
    __shared__ int s_is64;
    int t = threadIdx.x;
    // fast parallel dtype detect: int64 ids < 3070 => odd 32-bit words zero
    if (t < 32) {
        int val = (t < 8) ? ((const int*)eidx)[2 * t + 1] : 0;
        int any = __any_sync(0xffffffffu, val != 0);
        if (t == 0) s_is64 = !any;
    }
    __syncthreads();
    int is64 = s_is64;
    int i = blockIdx.x * 256 + t;
    if (i == 0) g_is64 = is64;
    if (i < 2 * NEDGES) g_present[load_eid(eidx, i, is64)] = 1;
    if (i < NNODES) { g_deg[i] = 1.0f; g_counts[i] = 0; }
    if (i < 128 * 64) {
        int k = i >> 6, c = i & 63;
        float v = 0.f;
        if (c < HS) {
            float s = 0.f;
            #pragma unroll 8
            for (int o = 0; o < NOUT; o++) s += W[k * NOUT + o] * W_ih[c * NOUT + o];
            v = __uint_as_float(to_tf32(s));
        }
        int t16 = k >> 4, j = k & 15, q = j >> 2, r = j & 3;
        int sct = 2 * t16 + (r >> 1);
        int bidx = r & 1;
        int klo = q;
        int jcol = c >> 3, nr = c & 7, jp = jcol >> 1, jodd = jcol & 1;
        int lane = nr * 4 + klo;
        g_Bfrag[(((sct * 4 + jp) * 32 + lane) << 2) + jodd * 2 + bidx] = v;
    }
    int ci = i - 128 * 64;
    if (ci >= 0 && ci < HS) {
        float s = b_ih[ci];
        #pragma unroll 8
        for (int o = 0; o < NOUT; o++) s += b[o] * W_ih[ci * NOUT + o];
        g_cvec[ci] = s;
    }
    if (ci == HS) { g_cvec[50] = 0.f; g_cvec[51] = 0.f; }
}

// ---------------- single-block exclusive scans ----------------
__global__ void k_scan(int mode) {
    __shared__ int sa[1024], sb[1024];
    int t = threadIdx.x;
    int base = t * 3;
    const int* in = mode ? g_counts : g_present;
    int v0 = (base     < NNODES) ? in[base]     : 0;
    int v1 = (base + 1 < NNODES) ? in[base + 1] : 0;
    int v2 = (base + 2 < NNODES) ? in[base + 2] : 0;
    int s = v0 + v1 + v2;
    sa[t] = s;
    __syncthreads();
    int* src = sa; int* dst = sb;
    for (int off = 1; off < 1024; off <<= 1) {
        int val = src[t];
        if (t >= off) val += src[t - off];
        dst[t] = val;
        __syncthreads();
        int* tmp = src; src = dst; dst = tmp;
    }
    int incl = src[t];
    int excl = incl - s;
    if (mode == 0) {
        if (base     < NNODES) g_rank[base]     = excl;
        if (base + 1 < NNODES) g_rank[base + 1] = excl + v0;
        if (base + 2 < NNODES) g_rank[base + 2] = excl + v0 + v1;
    } else {
        if (base < NNODES) {
            g_csrptr[base] = excl; g_cursor[base] = excl;
            g_dinv[base] = rsqrtf(g_deg[base]);
        }
        if (base + 1 < NNODES) {
            g_csrptr[base + 1] = excl + v0; g_cursor[base + 1] = excl + v0;
            g_dinv[base + 1] = rsqrtf(g_deg[base + 1]);
        }
        if (base + 2 < NNODES) {
            g_csrptr[base + 2] = excl + v0 + v1; g_cursor[base + 2] = excl + v0 + v1;
            g_dinv[base + 2] = rsqrtf(g_deg[base + 2]);
        }
        if (t == 1023) g_csrptr[NNODES] = incl;
    }
}

// ---------------- remap edges + degree/counts ----------------
__global__ void k_edges(const void* eidx, const float* __restrict__ ew) {
    int e = blockIdx.x * 256 + threadIdx.x;
    if (e >= NEDGES) return;
    int is64 = g_is64;
    int sid = load_eid(eidx, e, is64);
    int did = load_eid(eidx, NEDGES + e, is64);
    int s = g_rank[sid], d = g_rank[did];
    g_esrc[e] = s;
    g_edst[e] = d;
    atomicAdd(&g_deg[d], ew[e]);
    atomicAdd(&g_counts[d], 1);
}

// ---------------- fill CSR (by dst): packed (w, src*USTR) ----------------
__global__ void k_fill(const float* __restrict__ ew) {
    int e = blockIdx.x * 256 + threadIdx.x;
    if (e >= NEDGES) return;
    int d = g_edst[e], s = g_esrc[e];
    int pos = atomicAdd(&g_cursor[d], 1);
    g_epack[pos] = make_float2(g_dinv[s] * ew[e] * g_dinv[d],
                               __int_as_float(s * USTR));
}

// ---------------- GEMM: u = x @ M via mma.sync tf32 m16n8k8, fp16 out -----------
__global__ void __launch_bounds__(128) k_gemm(const float* __restrict__ x) {
    __shared__ __align__(16) float4 Bs[16 * 4 * 32];
    int tid = threadIdx.x, wid = tid >> 5, lane = tid & 31;
    {
        const float4* s = (const float4*)g_Bfrag;
        #pragma unroll
        for (int i = 0; i < 16; i++) Bs[tid + 128 * i] = s[tid + 128 * i];
    }
    size_t rowbase = (size_t)blockIdx.x * 128;
    int grp = lane >> 2, qid = lane & 3;
    const float* px = x + (rowbase + wid * 32 + grp) * NFEAT + 4 * qid;
    __syncthreads();

    float d[14][4];
    #pragma unroll
    for (int i = 0; i < 14; i++)
        #pragma unroll
        for (int j = 0; j < 4; j++) d[i][j] = 0.f;

    #pragma unroll
    for (int t = 0; t < 8; t++) {
        float4 v0 = *(const float4*)(px + 16 * t);
        float4 v1 = *(const float4*)(px + 8 * NFEAT + 16 * t);
        float4 v2 = *(const float4*)(px + 16 * NFEAT + 16 * t);
        float4 v3 = *(const float4*)(px + 24 * NFEAT + 16 * t);
        #pragma unroll
        for (int ss = 0; ss < 2; ss++) {
            int s = 2 * t + ss;
            uint32_t am0[4], am1[4];
            if (ss == 0) {
                am0[0] = to_tf32(v0.x); am0[1] = to_tf32(v1.x);
                am0[2] = to_tf32(v0.y); am0[3] = to_tf32(v1.y);
                am1[0] = to_tf32(v2.x); am1[1] = to_tf32(v3.x);
                am1[2] = to_tf32(v2.y); am1[3] = to_tf32(v3.y);
            } else {
                am0[0] = to_tf32(v0.z); am0[1] = to_tf32(v1.z);
                am0[2] = to_tf32(v0.w); am0[3] = to_tf32(v1.w);
                am1[0] = to_tf32(v2.z); am1[1] = to_tf32(v3.z);
                am1[2] = to_tf32(v2.w); am1[3] = to_tf32(v3.w);
            }
            float4 bv[4];
            #pragma unroll
            for (int jp = 0; jp < 4; jp++) bv[jp] = Bs[(s * 4 + jp) * 32 + lane];
            const uint32_t* bu = (const uint32_t*)bv;
            #pragma unroll
            for (int jt = 0; jt < 7; jt++) {
                uint32_t b0 = bu[jt * 2], b1 = bu[jt * 2 + 1];
                mma_tf32(d[jt], am0, b0, b1);
                mma_tf32(d[7 + jt], am1, b0, b1);
            }
        }
    }
    __half2 z2 = __float2half2_rn(0.f);
    #pragma unroll
    for (int mt = 0; mt < 2; mt++) {
        size_t r0 = rowbase + wid * 32 + mt * 16 + grp;
        __half* p0 = g_u + r0 * USTR;
        #pragma unroll
        for (int jt = 0; jt < 7; jt++) {
            int c0 = jt * 8 + 2 * qid;
            __half2 lo, hi;
            if (jt < 6 || qid == 0) {
                lo = __floats2half2_rn(d[mt * 7 + jt][0], d[mt * 7 + jt][1]);
                hi = __floats2half2_rn(d[mt * 7 + jt][2], d[mt * 7 + jt][3]);
            } else { lo = z2; hi = z2; }
            *(__half2*)(p0 + c0) = lo;
            *(__half2*)(p0 + 8 * USTR + c0) = hi;
        }
        int c0 = 56 + 2 * qid;
        *(__half2*)(p0 + c0) = z2;
        *(__half2*)(p0 + 8 * USTR + c0) = z2;
    }
}

// ---------------- SpMM: warp per (n,b), n-major; full-warp row gather -----------
__global__ void __launch_bounds__(256) k_spmm() {
    int gw = blockIdx.x * 8 + (threadIdx.x >> 5);
    int lane = threadIdx.x & 31;
    int n = gw >> 7;          // 128 batches per node, same n across CTA
    int b = gw & 127;
    const __half* ub = g_u + (size_t)b * (NNODES * USTR) + 2 * lane;
    int e0 = g_csrptr[n], e1 = g_csrptr[n + 1];
    float sx = 0.f, sy = 0.f;
    int e = e0;
    for (; e + 3 < e1; e += 4) {
        float2 m0 = g_epack[e],     m1 = g_epack[e + 1];
        float2 m2 = g_epack[e + 2], m3 = g_epack[e + 3];
        float2 f0 = __half22float2(*(const __half2*)(ub + __float_as_int(m0.y)));
        float2 f1 = __half22float2(*(const __half2*)(ub + __float_as_int(m1.y)));
        float2 f2 = __half22float2(*(const __half2*)(ub + __float_as_int(m2.y)));
        float2 f3 = __half22float2(*(const __half2*)(ub + __float_as_int(m3.y)));
        sx += m0.x * f0.x + m1.x * f1.x + m2.x * f2.x + m3.x * f3.x;
        sy += m0.x * f0.y + m1.x * f1.y + m2.x * f2.y + m3.x * f3.y;
    }
    for (; e < e1; e++) {
        float2 m0 = g_epack[e];
        float2 f0 = __half22float2(*(const __half2*)(ub + __float_as_int(m0.y)));
        sx += m0.x * f0.x;
        sy += m0.x * f0.y;
    }
    if (lane < 25) {
        float dv = g_dinv[n];
        float ws = dv * dv;
        float2 fs = __half22float2(*(const __half2*)(ub + n * USTR));
        float2 cv = *(const float2*)(g_cvec + 2 * lane);
        *(float2*)(g_pre + ((size_t)b * NNODES + n) * HSP + 2 * lane) =
            make_float2(sx + ws * fs.x + cv.x, sy + ws * fs.y + cv.y);
    }
}

// ---------------- RNN: warp per node, 128-thread CTAs, prefetch distance 2 ------
__global__ void __launch_bounds__(128) k_rnn(const float* __restrict__ Whh,
                                             const float* __restrict__ bhh,
                                             const float* __restrict__ h0,
                                             float* __restrict__ out) {
    int w = blockIdx.x * 4 + (threadIdx.x >> 5);
    int lane = threadIdx.x & 31;
    if (w >= NNODES) return;
    __shared__ __align__(16) float hsm[4][2][56];
    float* hc = hsm[threadIdx.x >> 5][0];
    float* hn = hsm[threadIdx.x >> 5][1];
    bool hi = lane < 18;
    int c1 = hi ? 32 + lane : 0;
    // pack W_hh rows into f32x2 pairs (26 per output col; pair 25 = 0)
    unsigned long long w0p[26], w1p[26];
    #pragma unroll
    for (int k = 0; k < 25; k++) {
        w0p[k] = pk2(Whh[lane * HS + 2 * k], Whh[lane * HS + 2 * k + 1]);
        w1p[k] = pk2(Whh[c1 * HS + 2 * k], Whh[c1 * HS + 2 * k + 1]);
    }
    unsigned long long zz = pk2(0.f, 0.f);
    w0p[25] = zz; w1p[25] = zz;
    float b0 = bhh[lane];
    float b1 = bhh[c1];
    hc[lane] = h0[(size_t)w * HS + lane];
    if (hi) hc[32 + lane] = h0[(size_t)w * HS + 32 + lane];
    if (lane == 0) { hc[50] = 0.f; hc[51] = 0.f; hn[50] = 0.f; hn[51] = 0.f; }
    __syncwarp();
    const float* prew = g_pre + (size_t)w * HSP;
    float* outw = out + (size_t)w * HS;
    const size_t pstr = (size_t)NNODES * HSP;
    const size_t ostr = (size_t)NNODES * HS;
    // prefetch distance 2: A holds even steps, B holds odd steps
    float pA0 = prew[lane];
    float pA1 = hi ? prew[32 + lane] : 0.f;
    float pB0 = prew[pstr + lane];
    float pB1 = hi ? prew[pstr + 32 + lane] : 0.f;
    prew += 2 * pstr;
    #pragma unroll 1
    for (int t = 0; t < NB; t += 2) {
        // ---- even step: consume A, prefetch t+2 into A ----
        {
            float a0 = pA0 + b0;
            float a1 = pA1 + b1;
            pA0 = prew[lane];
            pA1 = hi ? prew[32 + lane] : 0.f;
            unsigned long long acc0 = zz, acc1 = zz, acc2 = zz, acc3 = zz;
            #pragma unroll
            for (int kk = 0; kk < 13; kk++) {
                ulonglong2 hp = *(const ulonglong2*)&hc[kk * 4];
                acc0 = fma2(hp.x, w0p[2 * kk], acc0);
                acc1 = fma2(hp.y, w0p[2 * kk + 1], acc1);
                acc2 = fma2(hp.x, w1p[2 * kk], acc2);
                acc3 = fma2(hp.y, w1p[2 * kk + 1], acc3);
            }
            float2 u0 = upk2(acc0), u1 = upk2(acc1);
            float2 u2 = upk2(acc2), u3 = upk2(acc3);
            float t0 = fast_tanh(a0 + (u0.x + u0.y) + (u1.x + u1.y));
            float t1 = fast_tanh(a1 + (u2.x + u2.y) + (u3.x + u3.y));
            hn[lane] = t0;
            if (hi) hn[32 + lane] = t1;
            __syncwarp();
            float* tmp = hc; hc = hn; hn = tmp;
            outw[lane] = t0;
            if (hi) outw[32 + lane] = t1;
            outw += ostr;
        }
        // ---- odd step: consume B, prefetch t+3 into B ----
        {
            float a0 = pB0 + b0;
            float a1 = pB1 + b1;
            pB0 = prew[pstr + lane];
            pB1 = hi ? prew[pstr + 32 + lane] : 0.f;
            prew += 2 * pstr;
            unsigned long long acc0 = zz, acc1 = zz, acc2 = zz, acc3 = zz;
            #pragma unroll
            for (int kk = 0; kk < 13; kk++) {
                ulonglong2 hp = *(const ulonglong2*)&hc[kk * 4];
                acc0 = fma2(hp.x, w0p[2 * kk], acc0);
                acc1 = fma2(hp.y, w0p[2 * kk + 1], acc1);
                acc2 = fma2(hp.x, w1p[2 * kk], acc2);
                acc3 = fma2(hp.y, w1p[2 * kk + 1], acc3);
            }
            float2 u0 = upk2(acc0), u1 = upk2(acc1);
            float2 u2 = upk2(acc2), u3 = upk2(acc3);
            float t0 = fast_tanh(a0 + (u0.x + u0.y) + (u1.x + u1.y));
            float t1 = fast_tanh(a1 + (u2.x + u2.y) + (u3.x + u3.y));
            hn[lane] = t0;
            if (hi) hn[32 + lane] = t1;
            __syncwarp();
            float* tmp = hc; hc = hn; hn = tmp;
            outw[lane] = t0;
            if (hi) outw[32 + lane] = t1;
            outw += ostr;
        }
    }
}

// ---------------- launch ----------------
extern "C" void kernel_launch(void* const* d_in, const int* in_sizes, int n_in,
                              void* d_out, int out_size) {
    const float* x    = (const float*)d_in[0];
    const void*  eidx = d_in[1];
    const float* ew   = (const float*)d_in[2];
    const float* W    = (const float*)d_in[3];
    const float* b    = (const float*)d_in[4];
    const float* W_ih = (const float*)d_in[5];
    const float* W_hh = (const float*)d_in[6];
    const float* b_ih = (const float*)d_in[7];
    const float* b_hh = (const float*)d_in[8];
    const float* h0   = (const float*)d_in[9];
    float* out = (float*)d_out;

    k_setup<<<(2 * NEDGES + 255) / 256, 256>>>(eidx, W, b, W_ih, b_ih);  // 0
    k_scan<<<1, 1024>>>(0);                                  // 1
    k_edges<<<(NEDGES + 255) / 256, 256>>>(eidx, ew);        // 2
    k_gemm<<<NNODES, 128>>>(x);                              // 3  <- profiled (control)
    k_scan<<<1, 1024>>>(1);                                  // 4
    k_fill<<<(NEDGES + 255) / 256, 256>>>(ew);               // 5
    k_spmm<<<(NB * NNODES) / 8, 256>>>();                    // 6
    k_rnn<<<(NNODES + 3) / 4, 128>>>(W_hh, b_hh, h0, out);   // 7
}

// round 14
// speedup vs baseline: 1.3276x; 1.1144x over previous
#include <cuda_runtime.h>
#include <cuda_fp16.h>
#include <math.h>
#include <stdint.h>

#define NNODES 3070
#define NFEAT 128
#define NOUT 64
#define HS 50
#define HSP 52           // fp32 pre row: 52 floats
#define USTR 64          // fp16 u row: 64 halves = 128B (one cache line)
#define NEDGES 49120
#define NB 128
#define NROWS (NB * NNODES)

// ---------------- device scratch (static, no allocations) ----------------
__device__ int   g_is64;
__device__ int   g_present[NNODES];   // idempotent marks; never re-zeroed
__device__ int   g_rank[NNODES];
__device__ float g_deg[NNODES];
__device__ float g_dinv[NNODES];
__device__ int   g_counts[NNODES];
__device__ int   g_csrptr[NNODES + 1];
__device__ int   g_cursor[NNODES];
__device__ int   g_esrc[NEDGES];
__device__ int   g_edst[NEDGES];
__device__ __align__(8) float2 g_epack[NEDGES];  // (norm_w, src*USTR as int bits)
// B fragments in mma order: [s(16)][jp(4)][lane(32)][slot(4)] = 32KB
__device__ __align__(16) float g_Bfrag[16 * 4 * 32 * 4];
__device__ __align__(16) float g_cvec[HSP];
__device__ __align__(256) __half g_u[(size_t)NROWS * USTR];
// padded by TWO batch-rows so RNN prefetch distance 2 is branch-free
__device__ __align__(16) float g_pre[(size_t)(NROWS + 2 * NNODES) * HSP];

__device__ __forceinline__ uint32_t to_tf32(float f) {
    uint32_t r;
    asm("cvt.rna.tf32.f32 %0, %1;" : "=r"(r) : "f"(f));
    return r;
}
__device__ __forceinline__ void mma_tf32(float* d, const uint32_t* a,
                                         uint32_t b0, uint32_t b1) {
    asm volatile(
        "mma.sync.aligned.m16n8k8.row.col.f32.tf32.tf32.f32 "
        "{%0,%1,%2,%3}, {%4,%5,%6,%7}, {%8,%9}, {%0,%1,%2,%3};"
        : "+f"(d[0]), "+f"(d[1]), "+f"(d[2]), "+f"(d[3])
        : "r"(a[0]), "r"(a[1]), "r"(a[2]), "r"(a[3]), "r"(b0), "r"(b1));
}
// accurate fast tanh: ex2/rcp approx are ~2^-23 rel err -> ~1e-6 overall
__device__ __forceinline__ float fast_tanh(float x) {
    float e;
    asm("ex2.approx.f32 %0, %1;" : "=f"(e) : "f"(x * 2.8853900817779268f));
    float r;
    asm("rcp.approx.f32 %0, %1;" : "=f"(r) : "f"(e + 1.0f));
    return fmaf(-2.0f, r, 1.0f);
}
// packed f32x2 fma (Blackwell FFMA2, base sm_100+ feature)
__device__ __forceinline__ unsigned long long fma2(unsigned long long a,
                                                   unsigned long long b,
                                                   unsigned long long c) {
    unsigned long long d;
    asm("fma.rn.f32x2 %0, %1, %2, %3;" : "=l"(d) : "l"(a), "l"(b), "l"(c));
    return d;
}
__device__ __forceinline__ unsigned long long pk2(float x, float y) {
    unsigned long long r;
    asm("mov.b64 %0, {%1, %2};" : "=l"(r) : "f"(x), "f"(y));
    return r;
}
__device__ __forceinline__ float2 upk2(unsigned long long v) {
    float2 r;
    asm("mov.b64 {%0, %1}, %2;" : "=f"(r.x), "=f"(r.y) : "l"(v));
    return r;
}

__device__ __forceinline__ int load_eid(const void* eidx, int i, int is64) {
    if (is64) return (int)((const long long*)eidx)[i];
    return ((const int*)eidx)[i];
}

// ---------------- setup: mark + init + B fragments + cvec -----------------------
__global__ void k_setup(const void* eidx,
                        const float* __restrict__ W, const float* __restrict__ b,
                        const float* __restrict__ W_ih, const float* __restrict__ b_ih) {
    __shared__ int s_is64;
    int t = threadIdx.x;
    // fast parallel dtype detect: int64 ids < 3070 => odd 32-bit words zero
    if (t < 32) {
        int val = (t < 8) ? ((const int*)eidx)[2 * t + 1] : 0;
        int any = __any_sync(0xffffffffu, val != 0);
        if (t == 0) s_is64 = !any;
    }
    __syncthreads();
    int is64 = s_is64;
    int i = blockIdx.x * 256 + t;
    if (i == 0) g_is64 = is64;
    if (i < 2 * NEDGES) g_present[load_eid(eidx, i, is64)] = 1;
    if (i < NNODES) { g_deg[i] = 1.0f; g_counts[i] = 0; }
    if (i < 128 * 64) {
        int k = i >> 6, c = i & 63;
        float v = 0.f;
        if (c < HS) {
            float s = 0.f;
            #pragma unroll 8
            for (int o = 0; o < NOUT; o++) s += W[k * NOUT + o] * W_ih[c * NOUT + o];
            v = __uint_as_float(to_tf32(s));
        }
        int t16 = k >> 4, j = k & 15, q = j >> 2, r = j & 3;
        int sct = 2 * t16 + (r >> 1);
        int bidx = r & 1;
        int klo = q;
        int jcol = c >> 3, nr = c & 7, jp = jcol >> 1, jodd = jcol & 1;
        int lane = nr * 4 + klo;
        g_Bfrag[(((sct * 4 + jp) * 32 + lane) << 2) + jodd * 2 + bidx] = v;
    }
    int ci = i - 128 * 64;
    if (ci >= 0 && ci < HS) {
        float s = b_ih[ci];
        #pragma unroll 8
        for (int o = 0; o < NOUT; o++) s += b[o] * W_ih[ci * NOUT + o];
        g_cvec[ci] = s;
    }
    if (ci == HS) { g_cvec[50] = 0.f; g_cvec[51] = 0.f; }
}

// ---------------- single-block exclusive scans ----------------
__global__ void k_scan(int mode) {
    __shared__ int sa[1024], sb[1024];
    int t = threadIdx.x;
    int base = t * 3;
    const int* in = mode ? g_counts : g_present;
    int v0 = (base     < NNODES) ? in[base]     : 0;
    int v1 = (base + 1 < NNODES) ? in[base + 1] : 0;
    int v2 = (base + 2 < NNODES) ? in[base + 2] : 0;
    int s = v0 + v1 + v2;
    sa[t] = s;
    __syncthreads();
    int* src = sa; int* dst = sb;
    for (int off = 1; off < 1024; off <<= 1) {
        int val = src[t];
        if (t >= off) val += src[t - off];
        dst[t] = val;
        __syncthreads();
        int* tmp = src; src = dst; dst = tmp;
    }
    int incl = src[t];
    int excl = incl - s;
    if (mode == 0) {
        if (base     < NNODES) g_rank[base]     = excl;
        if (base + 1 < NNODES) g_rank[base + 1] = excl + v0;
        if (base + 2 < NNODES) g_rank[base + 2] = excl + v0 + v1;
    } else {
        if (base < NNODES) {
            g_csrptr[base] = excl; g_cursor[base] = excl;
            g_dinv[base] = rsqrtf(g_deg[base]);
        }
        if (base + 1 < NNODES) {
            g_csrptr[base + 1] = excl + v0; g_cursor[base + 1] = excl + v0;
            g_dinv[base + 1] = rsqrtf(g_deg[base + 1]);
        }
        if (base + 2 < NNODES) {
            g_csrptr[base + 2] = excl + v0 + v1; g_cursor[base + 2] = excl + v0 + v1;
            g_dinv[base + 2] = rsqrtf(g_deg[base + 2]);
        }
        if (t == 1023) g_csrptr[NNODES] = incl;
    }
}

// ---------------- remap edges + degree/counts ----------------
__global__ void k_edges(const void* eidx, const float* __restrict__ ew) {
    int e = blockIdx.x * 256 + threadIdx.x;
    if (e >= NEDGES) return;
    int is64 = g_is64;
    int sid = load_eid(eidx, e, is64);
    int did = load_eid(eidx, NEDGES + e, is64);
    int s = g_rank[sid], d = g_rank[did];
    g_esrc[e] = s;
    g_edst[e] = d;
    atomicAdd(&g_deg[d], ew[e]);
    atomicAdd(&g_counts[d], 1);
}

// ---------------- fill CSR (by dst): packed (w, src*USTR) ----------------
__global__ void k_fill(const float* __restrict__ ew) {
    int e = blockIdx.x * 256 + threadIdx.x;
    if (e >= NEDGES) return;
    int d = g_edst[e], s = g_esrc[e];
    int pos = atomicAdd(&g_cursor[d], 1);
    g_epack[pos] = make_float2(g_dinv[s] * ew[e] * g_dinv[d],
                               __int_as_float(s * USTR));
}

// ---------------- GEMM: u = x @ M via mma.sync tf32 m16n8k8, fp16 out -----------
__global__ void __launch_bounds__(128) k_gemm(const float* __restrict__ x) {
    __shared__ __align__(16) float4 Bs[16 * 4 * 32];
    int tid = threadIdx.x, wid = tid >> 5, lane = tid & 31;
    {
        const float4* s = (const float4*)g_Bfrag;
        #pragma unroll
        for (int i = 0; i < 16; i++) Bs[tid + 128 * i] = s[tid + 128 * i];
    }
    size_t rowbase = (size_t)blockIdx.x * 128;
    int grp = lane >> 2, qid = lane & 3;
    const float* px = x + (rowbase + wid * 32 + grp) * NFEAT + 4 * qid;
    __syncthreads();

    float d[14][4];
    #pragma unroll
    for (int i = 0; i < 14; i++)
        #pragma unroll
        for (int j = 0; j < 4; j++) d[i][j] = 0.f;

    #pragma unroll
    for (int t = 0; t < 8; t++) {
        float4 v0 = *(const float4*)(px + 16 * t);
        float4 v1 = *(const float4*)(px + 8 * NFEAT + 16 * t);
        float4 v2 = *(const float4*)(px + 16 * NFEAT + 16 * t);
        float4 v3 = *(const float4*)(px + 24 * NFEAT + 16 * t);
        #pragma unroll
        for (int ss = 0; ss < 2; ss++) {
            int s = 2 * t + ss;
            uint32_t am0[4], am1[4];
            if (ss == 0) {
                am0[0] = to_tf32(v0.x); am0[1] = to_tf32(v1.x);
                am0[2] = to_tf32(v0.y); am0[3] = to_tf32(v1.y);
                am1[0] = to_tf32(v2.x); am1[1] = to_tf32(v3.x);
                am1[2] = to_tf32(v2.y); am1[3] = to_tf32(v3.y);
            } else {
                am0[0] = to_tf32(v0.z); am0[1] = to_tf32(v1.z);
                am0[2] = to_tf32(v0.w); am0[3] = to_tf32(v1.w);
                am1[0] = to_tf32(v2.z); am1[1] = to_tf32(v3.z);
                am1[2] = to_tf32(v2.w); am1[3] = to_tf32(v3.w);
            }
            float4 bv[4];
            #pragma unroll
            for (int jp = 0; jp < 4; jp++) bv[jp] = Bs[(s * 4 + jp) * 32 + lane];
            const uint32_t* bu = (const uint32_t*)bv;
            #pragma unroll
            for (int jt = 0; jt < 7; jt++) {
                uint32_t b0 = bu[jt * 2], b1 = bu[jt * 2 + 1];
                mma_tf32(d[jt], am0, b0, b1);
                mma_tf32(d[7 + jt], am1, b0, b1);
            }
        }
    }
    __half2 z2 = __float2half2_rn(0.f);
    #pragma unroll
    for (int mt = 0; mt < 2; mt++) {
        size_t r0 = rowbase + wid * 32 + mt * 16 + grp;
        __half* p0 = g_u + r0 * USTR;
        #pragma unroll
        for (int jt = 0; jt < 7; jt++) {
            int c0 = jt * 8 + 2 * qid;
            __half2 lo, hi;
            if (jt < 6 || qid == 0) {
                lo = __floats2half2_rn(d[mt * 7 + jt][0], d[mt * 7 + jt][1]);
                hi = __floats2half2_rn(d[mt * 7 + jt][2], d[mt * 7 + jt][3]);
            } else { lo = z2; hi = z2; }
            *(__half2*)(p0 + c0) = lo;
            *(__half2*)(p0 + 8 * USTR + c0) = hi;
        }
        int c0 = 56 + 2 * qid;
        *(__half2*)(p0 + c0) = z2;
        *(__half2*)(p0 + 8 * USTR + c0) = z2;
    }
}

// ---------------- SpMM: warp per (n, batch-pair); shared metadata ---------------
// Lane l owns cols {2l, 2l+1}; per edge: 1 meta LDG + 2 u-row LDG (batches b0,b1).
// 196K warps, same occupancy as before (fewer waves), ~22% fewer instructions.
__global__ void __launch_bounds__(256) k_spmm() {
    int gw = blockIdx.x * 8 + (threadIdx.x >> 5);
    int lane = threadIdx.x & 31;
    int n = gw >> 6;          // 64 batch-pairs per node, same n across CTA
    int bp = gw & 63;
    const __half* ub0 = g_u + (size_t)(2 * bp) * (NNODES * USTR) + 2 * lane;
    const __half* ub1 = ub0 + (size_t)NNODES * USTR;
    int e0 = g_csrptr[n], e1 = g_csrptr[n + 1];
    float sx0 = 0.f, sy0 = 0.f, sx1 = 0.f, sy1 = 0.f;
    int e = e0;
    for (; e + 3 < e1; e += 4) {
        float2 m0 = g_epack[e],     m1 = g_epack[e + 1];
        float2 m2 = g_epack[e + 2], m3 = g_epack[e + 3];
        int o0 = __float_as_int(m0.y), o1 = __float_as_int(m1.y);
        int o2 = __float_as_int(m2.y), o3 = __float_as_int(m3.y);
        float2 a0 = __half22float2(*(const __half2*)(ub0 + o0));
        float2 b0 = __half22float2(*(const __half2*)(ub1 + o0));
        float2 a1 = __half22float2(*(const __half2*)(ub0 + o1));
        float2 b1 = __half22float2(*(const __half2*)(ub1 + o1));
        float2 a2 = __half22float2(*(const __half2*)(ub0 + o2));
        float2 b2 = __half22float2(*(const __half2*)(ub1 + o2));
        float2 a3 = __half22float2(*(const __half2*)(ub0 + o3));
        float2 b3 = __half22float2(*(const __half2*)(ub1 + o3));
        sx0 += m0.x * a0.x + m1.x * a1.x + m2.x * a2.x + m3.x * a3.x;
        sy0 += m0.x * a0.y + m1.x * a1.y + m2.x * a2.y + m3.x * a3.y;
        sx1 += m0.x * b0.x + m1.x * b1.x + m2.x * b2.x + m3.x * b3.x;
        sy1 += m0.x * b0.y + m1.x * b1.y + m2.x * b2.y + m3.x * b3.y;
    }
    for (; e < e1; e++) {
        float2 m0 = g_epack[e];
        int o0 = __float_as_int(m0.y);
        float2 a0 = __half22float2(*(const __half2*)(ub0 + o0));
        float2 b0 = __half22float2(*(const __half2*)(ub1 + o0));
        sx0 += m0.x * a0.x; sy0 += m0.x * a0.y;
        sx1 += m0.x * b0.x; sy1 += m0.x * b0.y;
    }
    if (lane < 25) {
        float dv = g_dinv[n];
        float ws = dv * dv;
        int so = n * USTR;
        float2 fs0 = __half22float2(*(const __half2*)(ub0 + so));
        float2 fs1 = __half22float2(*(const __half2*)(ub1 + so));
        float2 cv = *(const float2*)(g_cvec + 2 * lane);
        size_t p0 = ((size_t)(2 * bp) * NNODES + n) * HSP + 2 * lane;
        *(float2*)(g_pre + p0) =
            make_float2(sx0 + ws * fs0.x + cv.x, sy0 + ws * fs0.y + cv.y);
        *(float2*)(g_pre + p0 + (size_t)NNODES * HSP) =
            make_float2(sx1 + ws * fs1.x + cv.x, sy1 + ws * fs1.y + cv.y);
    }
}

// ---------------- RNN: warp per node, 128-thread CTAs, prefetch distance 2 ------
__global__ void __launch_bounds__(128) k_rnn(const float* __restrict__ Whh,
                                             const float* __restrict__ bhh,
                                             const float* __restrict__ h0,
                                             float* __restrict__ out) {
    int w = blockIdx.x * 4 + (threadIdx.x >> 5);
    int lane = threadIdx.x & 31;
    if (w >= NNODES) return;
    __shared__ __align__(16) float hsm[4][2][56];
    float* hc = hsm[threadIdx.x >> 5][0];
    float* hn = hsm[threadIdx.x >> 5][1];
    bool hi = lane < 18;
    int c1 = hi ? 32 + lane : 0;
    // pack W_hh rows into f32x2 pairs (26 per output col; pair 25 = 0)
    unsigned long long w0p[26], w1p[26];
    #pragma unroll
    for (int k = 0; k < 25; k++) {
        w0p[k] = pk2(Whh[lane * HS + 2 * k], Whh[lane * HS + 2 * k + 1]);
        w1p[k] = pk2(Whh[c1 * HS + 2 * k], Whh[c1 * HS + 2 * k + 1]);
    }
    unsigned long long zz = pk2(0.f, 0.f);
    w0p[25] = zz; w1p[25] = zz;
    float b0 = bhh[lane];
    float b1 = bhh[c1];
    hc[lane] = h0[(size_t)w * HS + lane];
    if (hi) hc[32 + lane] = h0[(size_t)w * HS + 32 + lane];
    if (lane == 0) { hc[50] = 0.f; hc[51] = 0.f; hn[50] = 0.f; hn[51] = 0.f; }
    __syncwarp();
    const float* prew = g_pre + (size_t)w * HSP;
    float* outw = out + (size_t)w * HS;
    const size_t pstr = (size_t)NNODES * HSP;
    const size_t ostr = (size_t)NNODES * HS;
    // prefetch distance 2: A holds even steps, B holds odd steps
    float pA0 = prew[lane];
    float pA1 = hi ? prew[32 + lane] : 0.f;
    float pB0 = prew[pstr + lane];
    float pB1 = hi ? prew[pstr + 32 + lane] : 0.f;
    prew += 2 * pstr;
    #pragma unroll 1
    for (int t = 0; t < NB; t += 2) {
        // ---- even step: consume A, prefetch t+2 into A ----
        {
            float a0 = pA0 + b0;
            float a1 = pA1 + b1;
            pA0 = prew[lane];
            pA1 = hi ? prew[32 + lane] : 0.f;
            unsigned long long acc0 = zz, acc1 = zz, acc2 = zz, acc3 = zz;
            #pragma unroll
            for (int kk = 0; kk < 13; kk++) {
                ulonglong2 hp = *(const ulonglong2*)&hc[kk * 4];
                acc0 = fma2(hp.x, w0p[2 * kk], acc0);
                acc1 = fma2(hp.y, w0p[2 * kk + 1], acc1);
                acc2 = fma2(hp.x, w1p[2 * kk], acc2);
                acc3 = fma2(hp.y, w1p[2 * kk + 1], acc3);
            }
            float2 u0 = upk2(acc0), u1 = upk2(acc1);
            float2 u2 = upk2(acc2), u3 = upk2(acc3);
            float t0 = fast_tanh(a0 + (u0.x + u0.y) + (u1.x + u1.y));
            float t1 = fast_tanh(a1 + (u2.x + u2.y) + (u3.x + u3.y));
            hn[lane] = t0;
            if (hi) hn[32 + lane] = t1;
            __syncwarp();
            float* tmp = hc; hc = hn; hn = tmp;
            outw[lane] = t0;
            if (hi) outw[32 + lane] = t1;
            outw += ostr;
        }
        // ---- odd step: consume B, prefetch t+3 into B ----
        {
            float a0 = pB0 + b0;
            float a1 = pB1 + b1;
            pB0 = prew[pstr + lane];
            pB1 = hi ? prew[pstr + 32 + lane] : 0.f;
            prew += 2 * pstr;
            unsigned long long acc0 = zz, acc1 = zz, acc2 = zz, acc3 = zz;
            #pragma unroll
            for (int kk = 0; kk < 13; kk++) {
                ulonglong2 hp = *(const ulonglong2*)&hc[kk * 4];
                acc0 = fma2(hp.x, w0p[2 * kk], acc0);
                acc1 = fma2(hp.y, w0p[2 * kk + 1], acc1);
                acc2 = fma2(hp.x, w1p[2 * kk], acc2);
                acc3 = fma2(hp.y, w1p[2 * kk + 1], acc3);
            }
            float2 u0 = upk2(acc0), u1 = upk2(acc1);
            float2 u2 = upk2(acc2), u3 = upk2(acc3);
            float t0 = fast_tanh(a0 + (u0.x + u0.y) + (u1.x + u1.y));
            float t1 = fast_tanh(a1 + (u2.x + u2.y) + (u3.x + u3.y));
            hn[lane] = t0;
            if (hi) hn[32 + lane] = t1;
            __syncwarp();
            float* tmp = hc; hc = hn; hn = tmp;
            outw[lane] = t0;
            if (hi) outw[32 + lane] = t1;
            outw += ostr;
        }
    }
}

// ---------------- launch ----------------
extern "C" void kernel_launch(void* const* d_in, const int* in_sizes, int n_in,
                              void* d_out, int out_size) {
    const float* x    = (const float*)d_in[0];
    const void*  eidx = d_in[1];
    const float* ew   = (const float*)d_in[2];
    const float* W    = (const float*)d_in[3];
    const float* b    = (const float*)d_in[4];
    const float* W_ih = (const float*)d_in[5];
    const float* W_hh = (const float*)d_in[6];
    const float* b_ih = (const float*)d_in[7];
    const float* b_hh = (const float*)d_in[8];
    const float* h0   = (const float*)d_in[9];
    float* out = (float*)d_out;

    k_setup<<<(2 * NEDGES + 255) / 256, 256>>>(eidx, W, b, W_ih, b_ih);  // 0
    k_scan<<<1, 1024>>>(0);                                  // 1
    k_edges<<<(NEDGES + 255) / 256, 256>>>(eidx, ew);        // 2
    k_gemm<<<NNODES, 128>>>(x);                              // 3  <- profiled (control)
    k_scan<<<1, 1024>>>(1);                                  // 4
    k_fill<<<(NEDGES + 255) / 256, 256>>>(ew);               // 5
    k_spmm<<<(NB * NNODES / 2) / 8, 256>>>();                // 6
    k_rnn<<<(NNODES + 3) / 4, 128>>>(W_hh, b_hh, h0, out);   // 7
}

// round 15
// speedup vs baseline: 1.3767x; 1.0370x over previous
#include <cuda_runtime.h>
#include <cuda_fp16.h>
#include <math.h>
#include <stdint.h>

#define NNODES 3070
#define NFEAT 128
#define NOUT 64
#define HS 50
#define HSP 52           // fp32 pre row: 52 floats
#define USTR 64          // fp16 u row: 64 halves = 128B (one cache line)
#define NEDGES 49120
#define NB 128
#define NROWS (NB * NNODES)

// ---------------- device scratch (static, no allocations) ----------------
__device__ int   g_is64;
__device__ int   g_present[NNODES];   // idempotent marks; never re-zeroed
__device__ int   g_rank[NNODES];
__device__ float g_deg[NNODES];
__device__ float g_dinv[NNODES];
__device__ int   g_counts[NNODES];
__device__ int   g_csrptr[NNODES + 1];
__device__ int   g_cursor[NNODES];
__device__ int   g_esrc[NEDGES];
__device__ int   g_edst[NEDGES];
__device__ __align__(8) float2 g_epack[NEDGES];  // (norm_w, src*USTR as int bits)
// B fragments in mma order: [s(16)][jp(4)][lane(32)][slot(4)] = 32KB
__device__ __align__(16) float g_Bfrag[16 * 4 * 32 * 4];
__device__ __align__(16) float g_cvec[HSP];
__device__ __align__(256) __half g_u[(size_t)NROWS * USTR];
// padded by FOUR batch-rows so RNN prefetch distance 4 is branch-free
__device__ __align__(16) float g_pre[(size_t)(NROWS + 4 * NNODES) * HSP];

__device__ __forceinline__ uint32_t to_tf32(float f) {
    uint32_t r;
    asm("cvt.rna.tf32.f32 %0, %1;" : "=r"(r) : "f"(f));
    return r;
}
__device__ __forceinline__ void mma_tf32(float* d, const uint32_t* a,
                                         uint32_t b0, uint32_t b1) {
    asm volatile(
        "mma.sync.aligned.m16n8k8.row.col.f32.tf32.tf32.f32 "
        "{%0,%1,%2,%3}, {%4,%5,%6,%7}, {%8,%9}, {%0,%1,%2,%3};"
        : "+f"(d[0]), "+f"(d[1]), "+f"(d[2]), "+f"(d[3])
        : "r"(a[0]), "r"(a[1]), "r"(a[2]), "r"(a[3]), "r"(b0), "r"(b1));
}
// accurate fast tanh: ex2/rcp approx are ~2^-23 rel err -> ~1e-6 overall
__device__ __forceinline__ float fast_tanh(float x) {
    float e;
    asm("ex2.approx.f32 %0, %1;" : "=f"(e) : "f"(x * 2.8853900817779268f));
    float r;
    asm("rcp.approx.f32 %0, %1;" : "=f"(r) : "f"(e + 1.0f));
    return fmaf(-2.0f, r, 1.0f);
}
// packed f32x2 fma (Blackwell FFMA2, base sm_100+ feature)
__device__ __forceinline__ unsigned long long fma2(unsigned long long a,
                                                   unsigned long long b,
                                                   unsigned long long c) {
    unsigned long long d;
    asm("fma.rn.f32x2 %0, %1, %2, %3;" : "=l"(d) : "l"(a), "l"(b), "l"(c));
    return d;
}
__device__ __forceinline__ unsigned long long pk2(float x, float y) {
    unsigned long long r;
    asm("mov.b64 %0, {%1, %2};" : "=l"(r) : "f"(x), "f"(y));
    return r;
}
__device__ __forceinline__ float2 upk2(unsigned long long v) {
    float2 r;
    asm("mov.b64 {%0, %1}, %2;" : "=f"(r.x), "=f"(r.y) : "l"(v));
    return r;
}

__device__ __forceinline__ int load_eid(const void* eidx, int i, int is64) {
    if (is64) return (int)((const long long*)eidx)[i];
    return ((const int*)eidx)[i];
}

// ---------------- setup: mark + init + B fragments + cvec -----------------------
__global__ void k_setup(const void* eidx,
                        const float* __restrict__ W, const float* __restrict__ b,
                        const float* __restrict__ W_ih, const float* __restrict__ b_ih) {
    __shared__ int s_is64;
    int t = threadIdx.x;
    if (t < 32) {
        int val = (t < 8) ? ((const int*)eidx)[2 * t + 1] : 0;
        int any = __any_sync(0xffffffffu, val != 0);
        if (t == 0) s_is64 = !any;
    }
    __syncthreads();
    int is64 = s_is64;
    int i = blockIdx.x * 256 + t;
    if (i == 0) g_is64 = is64;
    if (i < 2 * NEDGES) g_present[load_eid(eidx, i, is64)] = 1;
    if (i < NNODES) { g_deg[i] = 1.0f; g_counts[i] = 0; }
    if (i < 128 * 64) {
        int k = i >> 6, c = i & 63;
        float v = 0.f;
        if (c < HS) {
            float s = 0.f;
            #pragma unroll 8
            for (int o = 0; o < NOUT; o++) s += W[k * NOUT + o] * W_ih[c * NOUT + o];
            v = __uint_as_float(to_tf32(s));
        }
        int t16 = k >> 4, j = k & 15, q = j >> 2, r = j & 3;
        int sct = 2 * t16 + (r >> 1);
        int bidx = r & 1;
        int klo = q;
        int jcol = c >> 3, nr = c & 7, jp = jcol >> 1, jodd = jcol & 1;
        int lane = nr * 4 + klo;
        g_Bfrag[(((sct * 4 + jp) * 32 + lane) << 2) + jodd * 2 + bidx] = v;
    }
    int ci = i - 128 * 64;
    if (ci >= 0 && ci < HS) {
        float s = b_ih[ci];
        #pragma unroll 8
        for (int o = 0; o < NOUT; o++) s += b[o] * W_ih[ci * NOUT + o];
        g_cvec[ci] = s;
    }
    if (ci == HS) { g_cvec[50] = 0.f; g_cvec[51] = 0.f; }
}

// ---------------- single-block exclusive scans ----------------
__global__ void k_scan(int mode) {
    __shared__ int sa[1024], sb[1024];
    int t = threadIdx.x;
    int base = t * 3;
    const int* in = mode ? g_counts : g_present;
    int v0 = (base     < NNODES) ? in[base]     : 0;
    int v1 = (base + 1 < NNODES) ? in[base + 1] : 0;
    int v2 = (base + 2 < NNODES) ? in[base + 2] : 0;
    int s = v0 + v1 + v2;
    sa[t] = s;
    __syncthreads();
    int* src = sa; int* dst = sb;
    for (int off = 1; off < 1024; off <<= 1) {
        int val = src[t];
        if (t >= off) val += src[t - off];
        dst[t] = val;
        __syncthreads();
        int* tmp = src; src = dst; dst = tmp;
    }
    int incl = src[t];
    int excl = incl - s;
    if (mode == 0) {
        if (base     < NNODES) g_rank[base]     = excl;
        if (base + 1 < NNODES) g_rank[base + 1] = excl + v0;
        if (base + 2 < NNODES) g_rank[base + 2] = excl + v0 + v1;
    } else {
        if (base < NNODES) {
            g_csrptr[base] = excl; g_cursor[base] = excl;
            g_dinv[base] = rsqrtf(g_deg[base]);
        }
        if (base + 1 < NNODES) {
            g_csrptr[base + 1] = excl + v0; g_cursor[base + 1] = excl + v0;
            g_dinv[base + 1] = rsqrtf(g_deg[base + 1]);
        }
        if (base + 2 < NNODES) {
            g_csrptr[base + 2] = excl + v0 + v1; g_cursor[base + 2] = excl + v0 + v1;
            g_dinv[base + 2] = rsqrtf(g_deg[base + 2]);
        }
        if (t == 1023) g_csrptr[NNODES] = incl;
    }
}

// ---------------- remap edges + degree/counts ----------------
__global__ void k_edges(const void* eidx, const float* __restrict__ ew) {
    int e = blockIdx.x * 256 + threadIdx.x;
    if (e >= NEDGES) return;
    int is64 = g_is64;
    int sid = load_eid(eidx, e, is64);
    int did = load_eid(eidx, NEDGES + e, is64);
    int s = g_rank[sid], d = g_rank[did];
    g_esrc[e] = s;
    g_edst[e] = d;
    atomicAdd(&g_deg[d], ew[e]);
    atomicAdd(&g_counts[d], 1);
}

// ---------------- fill CSR (by dst): packed (w, src*USTR) ----------------
__global__ void k_fill(const float* __restrict__ ew) {
    int e = blockIdx.x * 256 + threadIdx.x;
    if (e >= NEDGES) return;
    int d = g_edst[e], s = g_esrc[e];
    int pos = atomicAdd(&g_cursor[d], 1);
    g_epack[pos] = make_float2(g_dinv[s] * ew[e] * g_dinv[d],
                               __int_as_float(s * USTR));
}

// ---------------- GEMM: u = x @ M via mma.sync tf32 m16n8k8, fp16 out -----------
__global__ void __launch_bounds__(128) k_gemm(const float* __restrict__ x) {
    __shared__ __align__(16) float4 Bs[16 * 4 * 32];
    int tid = threadIdx.x, wid = tid >> 5, lane = tid & 31;
    {
        const float4* s = (const float4*)g_Bfrag;
        #pragma unroll
        for (int i = 0; i < 16; i++) Bs[tid + 128 * i] = s[tid + 128 * i];
    }
    size_t rowbase = (size_t)blockIdx.x * 128;
    int grp = lane >> 2, qid = lane & 3;
    const float* px = x + (rowbase + wid * 32 + grp) * NFEAT + 4 * qid;
    __syncthreads();

    float d[14][4];
    #pragma unroll
    for (int i = 0; i < 14; i++)
        #pragma unroll
        for (int j = 0; j < 4; j++) d[i][j] = 0.f;

    #pragma unroll
    for (int t = 0; t < 8; t++) {
        float4 v0 = *(const float4*)(px + 16 * t);
        float4 v1 = *(const float4*)(px + 8 * NFEAT + 16 * t);
        float4 v2 = *(const float4*)(px + 16 * NFEAT + 16 * t);
        float4 v3 = *(const float4*)(px + 24 * NFEAT + 16 * t);
        #pragma unroll
        for (int ss = 0; ss < 2; ss++) {
            int s = 2 * t + ss;
            uint32_t am0[4], am1[4];
            if (ss == 0) {
                am0[0] = to_tf32(v0.x); am0[1] = to_tf32(v1.x);
                am0[2] = to_tf32(v0.y); am0[3] = to_tf32(v1.y);
                am1[0] = to_tf32(v2.x); am1[1] = to_tf32(v3.x);
                am1[2] = to_tf32(v2.y); am1[3] = to_tf32(v3.y);
            } else {
                am0[0] = to_tf32(v0.z); am0[1] = to_tf32(v1.z);
                am0[2] = to_tf32(v0.w); am0[3] = to_tf32(v1.w);
                am1[0] = to_tf32(v2.z); am1[1] = to_tf32(v3.z);
                am1[2] = to_tf32(v2.w); am1[3] = to_tf32(v3.w);
            }
            float4 bv[4];
            #pragma unroll
            for (int jp = 0; jp < 4; jp++) bv[jp] = Bs[(s * 4 + jp) * 32 + lane];
            const uint32_t* bu = (const uint32_t*)bv;
            #pragma unroll
            for (int jt = 0; jt < 7; jt++) {
                uint32_t b0 = bu[jt * 2], b1 = bu[jt * 2 + 1];
                mma_tf32(d[jt], am0, b0, b1);
                mma_tf32(d[7 + jt], am1, b0, b1);
            }
        }
    }
    __half2 z2 = __float2half2_rn(0.f);
    #pragma unroll
    for (int mt = 0; mt < 2; mt++) {
        size_t r0 = rowbase + wid * 32 + mt * 16 + grp;
        __half* p0 = g_u + r0 * USTR;
        #pragma unroll
        for (int jt = 0; jt < 7; jt++) {
            int c0 = jt * 8 + 2 * qid;
            __half2 lo, hi;
            if (jt < 6 || qid == 0) {
                lo = __floats2half2_rn(d[mt * 7 + jt][0], d[mt * 7 + jt][1]);
                hi = __floats2half2_rn(d[mt * 7 + jt][2], d[mt * 7 + jt][3]);
            } else { lo = z2; hi = z2; }
            *(__half2*)(p0 + c0) = lo;
            *(__half2*)(p0 + 8 * USTR + c0) = hi;
        }
        int c0 = 56 + 2 * qid;
        *(__half2*)(p0 + c0) = z2;
        *(__half2*)(p0 + 8 * USTR + c0) = z2;
    }
}

// ---------------- SpMM: warp per (n, batch-quad); shared metadata ---------------
// Lane l owns cols {2l, 2l+1}; per edge: 1 meta LDG + 4 u-row LDG (4 batches).
__global__ void __launch_bounds__(256) k_spmm() {
    int gw = blockIdx.x * 8 + (threadIdx.x >> 5);
    int lane = threadIdx.x & 31;
    int n = gw >> 5;          // 32 batch-quads per node
    int bq = gw & 31;
    const size_t P = (size_t)NNODES * USTR;
    const __half* ub0 = g_u + (size_t)(4 * bq) * P + 2 * lane;
    const __half* ub1 = ub0 + P;
    const __half* ub2 = ub0 + 2 * P;
    const __half* ub3 = ub0 + 3 * P;
    int e0 = g_csrptr[n], e1 = g_csrptr[n + 1];
    float sx0 = 0.f, sy0 = 0.f, sx1 = 0.f, sy1 = 0.f;
    float sx2 = 0.f, sy2 = 0.f, sx3 = 0.f, sy3 = 0.f;
    int e = e0;
    for (; e + 1 < e1; e += 2) {
        float2 m0 = g_epack[e], m1 = g_epack[e + 1];
        int o0 = __float_as_int(m0.y), o1 = __float_as_int(m1.y);
        float2 a0 = __half22float2(*(const __half2*)(ub0 + o0));
        float2 b0 = __half22float2(*(const __half2*)(ub1 + o0));
        float2 c0 = __half22float2(*(const __half2*)(ub2 + o0));
        float2 d0 = __half22float2(*(const __half2*)(ub3 + o0));
        float2 a1 = __half22float2(*(const __half2*)(ub0 + o1));
        float2 b1 = __half22float2(*(const __half2*)(ub1 + o1));
        float2 c1 = __half22float2(*(const __half2*)(ub2 + o1));
        float2 d1 = __half22float2(*(const __half2*)(ub3 + o1));
        sx0 += m0.x * a0.x + m1.x * a1.x;
        sy0 += m0.x * a0.y + m1.x * a1.y;
        sx1 += m0.x * b0.x + m1.x * b1.x;
        sy1 += m0.x * b0.y + m1.x * b1.y;
        sx2 += m0.x * c0.x + m1.x * c1.x;
        sy2 += m0.x * c0.y + m1.x * c1.y;
        sx3 += m0.x * d0.x + m1.x * d1.x;
        sy3 += m0.x * d0.y + m1.x * d1.y;
    }
    if (e < e1) {
        float2 m0 = g_epack[e];
        int o0 = __float_as_int(m0.y);
        float2 a0 = __half22float2(*(const __half2*)(ub0 + o0));
        float2 b0 = __half22float2(*(const __half2*)(ub1 + o0));
        float2 c0 = __half22float2(*(const __half2*)(ub2 + o0));
        float2 d0 = __half22float2(*(const __half2*)(ub3 + o0));
        sx0 += m0.x * a0.x; sy0 += m0.x * a0.y;
        sx1 += m0.x * b0.x; sy1 += m0.x * b0.y;
        sx2 += m0.x * c0.x; sy2 += m0.x * c0.y;
        sx3 += m0.x * d0.x; sy3 += m0.x * d0.y;
    }
    if (lane < 25) {
        float dv = g_dinv[n];
        float ws = dv * dv;
        int so = n * USTR;
        float2 fs0 = __half22float2(*(const __half2*)(ub0 + so));
        float2 fs1 = __half22float2(*(const __half2*)(ub1 + so));
        float2 fs2 = __half22float2(*(const __half2*)(ub2 + so));
        float2 fs3 = __half22float2(*(const __half2*)(ub3 + so));
        float2 cv = *(const float2*)(g_cvec + 2 * lane);
        const size_t Q = (size_t)NNODES * HSP;
        size_t p0 = ((size_t)(4 * bq) * NNODES + n) * HSP + 2 * lane;
        *(float2*)(g_pre + p0) =
            make_float2(sx0 + ws * fs0.x + cv.x, sy0 + ws * fs0.y + cv.y);
        *(float2*)(g_pre + p0 + Q) =
            make_float2(sx1 + ws * fs1.x + cv.x, sy1 + ws * fs1.y + cv.y);
        *(float2*)(g_pre + p0 + 2 * Q) =
            make_float2(sx2 + ws * fs2.x + cv.x, sy2 + ws * fs2.y + cv.y);
        *(float2*)(g_pre + p0 + 3 * Q) =
            make_float2(sx3 + ws * fs3.x + cv.x, sy3 + ws * fs3.y + cv.y);
    }
}

// ---------------- RNN: warp per node, 128-thread CTAs, prefetch distance 4 ------
__global__ void __launch_bounds__(128) k_rnn(const float* __restrict__ Whh,
                                             const float* __restrict__ bhh,
                                             const float* __restrict__ h0,
                                             float* __restrict__ out) {
    int w = blockIdx.x * 4 + (threadIdx.x >> 5);
    int lane = threadIdx.x & 31;
    if (w >= NNODES) return;
    __shared__ __align__(16) float hsm[4][2][56];
    float* hc = hsm[threadIdx.x >> 5][0];
    float* hn = hsm[threadIdx.x >> 5][1];
    bool hi = lane < 18;
    int c1 = hi ? 32 + lane : 0;
    // pack W_hh rows into f32x2 pairs (26 per output col; pair 25 = 0)
    unsigned long long w0p[26], w1p[26];
    #pragma unroll
    for (int k = 0; k < 25; k++) {
        w0p[k] = pk2(Whh[lane * HS + 2 * k], Whh[lane * HS + 2 * k + 1]);
        w1p[k] = pk2(Whh[c1 * HS + 2 * k], Whh[c1 * HS + 2 * k + 1]);
    }
    unsigned long long zz = pk2(0.f, 0.f);
    w0p[25] = zz; w1p[25] = zz;
    float b0 = bhh[lane];
    float b1 = bhh[c1];
    hc[lane] = h0[(size_t)w * HS + lane];
    if (hi) hc[32 + lane] = h0[(size_t)w * HS + 32 + lane];
    if (lane == 0) { hc[50] = 0.f; hc[51] = 0.f; hn[50] = 0.f; hn[51] = 0.f; }
    __syncwarp();
    const float* prew = g_pre + (size_t)w * HSP;
    float* outw = out + (size_t)w * HS;
    const size_t pstr = (size_t)NNODES * HSP;
    const size_t ostr = (size_t)NNODES * HS;
    // prefetch distance 4
    float pf0[4], pf1[4];
    #pragma unroll
    for (int j = 0; j < 4; j++) {
        pf0[j] = prew[j * pstr + lane];
        pf1[j] = hi ? prew[j * pstr + 32 + lane] : 0.f;
    }
    prew += 4 * pstr;
    #pragma unroll 1
    for (int t = 0; t < NB; t += 4) {
        #pragma unroll
        for (int j = 0; j < 4; j++) {
            float a0 = pf0[j] + b0;
            float a1 = pf1[j] + b1;
            pf0[j] = prew[j * pstr + lane];
            pf1[j] = hi ? prew[j * pstr + 32 + lane] : 0.f;
            unsigned long long acc0 = zz, acc1 = zz, acc2 = zz, acc3 = zz;
            #pragma unroll
            for (int kk = 0; kk < 13; kk++) {
                ulonglong2 hp = *(const ulonglong2*)&hc[kk * 4];
                acc0 = fma2(hp.x, w0p[2 * kk], acc0);
                acc1 = fma2(hp.y, w0p[2 * kk + 1], acc1);
                acc2 = fma2(hp.x, w1p[2 * kk], acc2);
                acc3 = fma2(hp.y, w1p[2 * kk + 1], acc3);
            }
            float2 u0 = upk2(acc0), u1 = upk2(acc1);
            float2 u2 = upk2(acc2), u3 = upk2(acc3);
            float t0 = fast_tanh(a0 + (u0.x + u0.y) + (u1.x + u1.y));
            float t1 = fast_tanh(a1 + (u2.x + u2.y) + (u3.x + u3.y));
            hn[lane] = t0;
            if (hi) hn[32 + lane] = t1;
            __syncwarp();
            float* tmp = hc; hc = hn; hn = tmp;
            outw[lane] = t0;
            if (hi) outw[32 + lane] = t1;
            outw += ostr;
        }
        prew += 4 * pstr;
    }
}

// ---------------- launch ----------------
extern "C" void kernel_launch(void* const* d_in, const int* in_sizes, int n_in,
                              void* d_out, int out_size) {
    const float* x    = (const float*)d_in[0];
    const void*  eidx = d_in[1];
    const float* ew   = (const float*)d_in[2];
    const float* W    = (const float*)d_in[3];
    const float* b    = (const float*)d_in[4];
    const float* W_ih = (const float*)d_in[5];
    const float* W_hh = (const float*)d_in[6];
    const float* b_ih = (const float*)d_in[7];
    const float* b_hh = (const float*)d_in[8];
    const float* h0   = (const float*)d_in[9];
    float* out = (float*)d_out;

    k_setup<<<(2 * NEDGES + 255) / 256, 256>>>(eidx, W, b, W_ih, b_ih);  // 0
    k_scan<<<1, 1024>>>(0);                                  // 1
    k_edges<<<(NEDGES + 255) / 256, 256>>>(eidx, ew);        // 2
    k_gemm<<<NNODES, 128>>>(x);                              // 3  <- profiled (control)
    k_scan<<<1, 1024>>>(1);                                  // 4
    k_fill<<<(NEDGES + 255) / 256, 256>>>(ew);               // 5
    k_spmm<<<(NB * NNODES / 4) / 8, 256>>>();                // 6
    k_rnn<<<(NNODES + 3) / 4, 128>>>(W_hh, b_hh, h0, out);   // 7
}

// round 16
// speedup vs baseline: 1.4385x; 1.0449x over previous
#include <cuda_runtime.h>
#include <cuda_fp16.h>
#include <math.h>
#include <stdint.h>

#define NNODES 3070
#define NFEAT 128
#define NOUT 64
#define HS 50
#define HSP 52           // cvec padding only
#define USTR 64          // fp16 u row: 64 halves = 128B (one cache line)
#define PSTR 64          // fp16 pre row: 64 halves = 128B
#define NEDGES 49120
#define NB 128
#define NROWS (NB * NNODES)

// ---------------- device scratch (static, no allocations) ----------------
__device__ int   g_is64;
__device__ int   g_present[NNODES];   // idempotent marks; never re-zeroed
__device__ int   g_rank[NNODES];
__device__ float g_deg[NNODES];
__device__ float g_dinv[NNODES];
__device__ int   g_counts[NNODES];
__device__ int   g_csrptr[NNODES + 1];
__device__ int   g_cursor[NNODES];
__device__ int   g_esrc[NEDGES];
__device__ int   g_edst[NEDGES];
__device__ __align__(8) float2 g_epack[NEDGES];  // (norm_w, src*USTR as int bits)
// B fragments in mma order: [s(16)][jp(4)][lane(32)][slot(4)] = 32KB
__device__ __align__(16) float g_Bfrag[16 * 4 * 32 * 4];
__device__ __align__(16) float g_cvec[HSP];
__device__ __align__(256) __half g_u[(size_t)NROWS * USTR];
// fp16 pre, padded by FOUR batch-rows for branch-free distance-4 prefetch
__device__ __align__(256) __half g_pre[(size_t)(NROWS + 4 * NNODES) * PSTR];

__device__ __forceinline__ uint32_t to_tf32(float f) {
    uint32_t r;
    asm("cvt.rna.tf32.f32 %0, %1;" : "=r"(r) : "f"(f));
    return r;
}
__device__ __forceinline__ void mma_tf32(float* d, const uint32_t* a,
                                         uint32_t b0, uint32_t b1) {
    asm volatile(
        "mma.sync.aligned.m16n8k8.row.col.f32.tf32.tf32.f32 "
        "{%0,%1,%2,%3}, {%4,%5,%6,%7}, {%8,%9}, {%0,%1,%2,%3};"
        : "+f"(d[0]), "+f"(d[1]), "+f"(d[2]), "+f"(d[3])
        : "r"(a[0]), "r"(a[1]), "r"(a[2]), "r"(a[3]), "r"(b0), "r"(b1));
}
// accurate fast tanh: ex2/rcp approx are ~2^-23 rel err -> ~1e-6 overall
__device__ __forceinline__ float fast_tanh(float x) {
    float e;
    asm("ex2.approx.f32 %0, %1;" : "=f"(e) : "f"(x * 2.8853900817779268f));
    float r;
    asm("rcp.approx.f32 %0, %1;" : "=f"(r) : "f"(e + 1.0f));
    return fmaf(-2.0f, r, 1.0f);
}
// packed f32x2 fma (Blackwell FFMA2, base sm_100+ feature)
__device__ __forceinline__ unsigned long long fma2(unsigned long long a,
                                                   unsigned long long b,
                                                   unsigned long long c) {
    unsigned long long d;
    asm("fma.rn.f32x2 %0, %1, %2, %3;" : "=l"(d) : "l"(a), "l"(b), "l"(c));
    return d;
}
__device__ __forceinline__ unsigned long long pk2(float x, float y) {
    unsigned long long r;
    asm("mov.b64 %0, {%1, %2};" : "=l"(r) : "f"(x), "f"(y));
    return r;
}
__device__ __forceinline__ float2 upk2(unsigned long long v) {
    float2 r;
    asm("mov.b64 {%0, %1}, %2;" : "=f"(r.x), "=f"(r.y) : "l"(v));
    return r;
}

__device__ __forceinline__ int load_eid(const void* eidx, int i, int is64) {
    if (is64) return (int)((const long long*)eidx)[i];
    return ((const int*)eidx)[i];
}

// ---------------- setup: mark + init + B fragments + cvec -----------------------
__global__ void k_setup(const void* eidx,
                        const float* __restrict__ W, const float* __restrict__ b,
                        const float* __restrict__ W_ih, const float* __restrict__ b_ih) {
    __shared__ int s_is64;
    int t = threadIdx.x;
    if (t < 32) {
        int val = (t < 8) ? ((const int*)eidx)[2 * t + 1] : 0;
        int any = __any_sync(0xffffffffu, val != 0);
        if (t == 0) s_is64 = !any;
    }
    __syncthreads();
    int is64 = s_is64;
    int i = blockIdx.x * 256 + t;
    if (i == 0) g_is64 = is64;
    if (i < 2 * NEDGES) g_present[load_eid(eidx, i, is64)] = 1;
    if (i < NNODES) { g_deg[i] = 1.0f; g_counts[i] = 0; }
    if (i < 128 * 64) {
        int k = i >> 6, c = i & 63;
        float v = 0.f;
        if (c < HS) {
            float s = 0.f;
            #pragma unroll 8
            for (int o = 0; o < NOUT; o++) s += W[k * NOUT + o] * W_ih[c * NOUT + o];
            v = __uint_as_float(to_tf32(s));
        }
        int t16 = k >> 4, j = k & 15, q = j >> 2, r = j & 3;
        int sct = 2 * t16 + (r >> 1);
        int bidx = r & 1;
        int klo = q;
        int jcol = c >> 3, nr = c & 7, jp = jcol >> 1, jodd = jcol & 1;
        int lane = nr * 4 + klo;
        g_Bfrag[(((sct * 4 + jp) * 32 + lane) << 2) + jodd * 2 + bidx] = v;
    }
    int ci = i - 128 * 64;
    if (ci >= 0 && ci < HS) {
        float s = b_ih[ci];
        #pragma unroll 8
        for (int o = 0; o < NOUT; o++) s += b[o] * W_ih[ci * NOUT + o];
        g_cvec[ci] = s;
    }
    if (ci == HS) { g_cvec[50] = 0.f; g_cvec[51] = 0.f; }
}

// ---------------- single-block exclusive scans ----------------
__global__ void k_scan(int mode) {
    __shared__ int sa[1024], sb[1024];
    int t = threadIdx.x;
    int base = t * 3;
    const int* in = mode ? g_counts : g_present;
    int v0 = (base     < NNODES) ? in[base]     : 0;
    int v1 = (base + 1 < NNODES) ? in[base + 1] : 0;
    int v2 = (base + 2 < NNODES) ? in[base + 2] : 0;
    int s = v0 + v1 + v2;
    sa[t] = s;
    __syncthreads();
    int* src = sa; int* dst = sb;
    for (int off = 1; off < 1024; off <<= 1) {
        int val = src[t];
        if (t >= off) val += src[t - off];
        dst[t] = val;
        __syncthreads();
        int* tmp = src; src = dst; dst = tmp;
    }
    int incl = src[t];
    int excl = incl - s;
    if (mode == 0) {
        if (base     < NNODES) g_rank[base]     = excl;
        if (base + 1 < NNODES) g_rank[base + 1] = excl + v0;
        if (base + 2 < NNODES) g_rank[base + 2] = excl + v0 + v1;
    } else {
        if (base < NNODES) {
            g_csrptr[base] = excl; g_cursor[base] = excl;
            g_dinv[base] = rsqrtf(g_deg[base]);
        }
        if (base + 1 < NNODES) {
            g_csrptr[base + 1] = excl + v0; g_cursor[base + 1] = excl + v0;
            g_dinv[base + 1] = rsqrtf(g_deg[base + 1]);
        }
        if (base + 2 < NNODES) {
            g_csrptr[base + 2] = excl + v0 + v1; g_cursor[base + 2] = excl + v0 + v1;
            g_dinv[base + 2] = rsqrtf(g_deg[base + 2]);
        }
        if (t == 1023) g_csrptr[NNODES] = incl;
    }
}

// ---------------- remap edges + degree/counts ----------------
__global__ void k_edges(const void* eidx, const float* __restrict__ ew) {
    int e = blockIdx.x * 256 + threadIdx.x;
    if (e >= NEDGES) return;
    int is64 = g_is64;
    int sid = load_eid(eidx, e, is64);
    int did = load_eid(eidx, NEDGES + e, is64);
    int s = g_rank[sid], d = g_rank[did];
    g_esrc[e] = s;
    g_edst[e] = d;
    atomicAdd(&g_deg[d], ew[e]);
    atomicAdd(&g_counts[d], 1);
}

// ---------------- fill CSR (by dst): packed (w, src*USTR) ----------------
__global__ void k_fill(const float* __restrict__ ew) {
    int e = blockIdx.x * 256 + threadIdx.x;
    if (e >= NEDGES) return;
    int d = g_edst[e], s = g_esrc[e];
    int pos = atomicAdd(&g_cursor[d], 1);
    g_epack[pos] = make_float2(g_dinv[s] * ew[e] * g_dinv[d],
                               __int_as_float(s * USTR));
}

// ---------------- GEMM: u = x @ M via mma.sync tf32 m16n8k8, fp16 out -----------
__global__ void __launch_bounds__(128) k_gemm(const float* __restrict__ x) {
    __shared__ __align__(16) float4 Bs[16 * 4 * 32];
    int tid = threadIdx.x, wid = tid >> 5, lane = tid & 31;
    {
        const float4* s = (const float4*)g_Bfrag;
        #pragma unroll
        for (int i = 0; i < 16; i++) Bs[tid + 128 * i] = s[tid + 128 * i];
    }
    size_t rowbase = (size_t)blockIdx.x * 128;
    int grp = lane >> 2, qid = lane & 3;
    const float* px = x + (rowbase + wid * 32 + grp) * NFEAT + 4 * qid;
    __syncthreads();

    float d[14][4];
    #pragma unroll
    for (int i = 0; i < 14; i++)
        #pragma unroll
        for (int j = 0; j < 4; j++) d[i][j] = 0.f;

    #pragma unroll
    for (int t = 0; t < 8; t++) {
        float4 v0 = *(const float4*)(px + 16 * t);
        float4 v1 = *(const float4*)(px + 8 * NFEAT + 16 * t);
        float4 v2 = *(const float4*)(px + 16 * NFEAT + 16 * t);
        float4 v3 = *(const float4*)(px + 24 * NFEAT + 16 * t);
        #pragma unroll
        for (int ss = 0; ss < 2; ss++) {
            int s = 2 * t + ss;
            uint32_t am0[4], am1[4];
            if (ss == 0) {
                am0[0] = to_tf32(v0.x); am0[1] = to_tf32(v1.x);
                am0[2] = to_tf32(v0.y); am0[3] = to_tf32(v1.y);
                am1[0] = to_tf32(v2.x); am1[1] = to_tf32(v3.x);
                am1[2] = to_tf32(v2.y); am1[3] = to_tf32(v3.y);
            } else {
                am0[0] = to_tf32(v0.z); am0[1] = to_tf32(v1.z);
                am0[2] = to_tf32(v0.w); am0[3] = to_tf32(v1.w);
                am1[0] = to_tf32(v2.z); am1[1] = to_tf32(v3.z);
                am1[2] = to_tf32(v2.w); am1[3] = to_tf32(v3.w);
            }
            float4 bv[4];
            #pragma unroll
            for (int jp = 0; jp < 4; jp++) bv[jp] = Bs[(s * 4 + jp) * 32 + lane];
            const uint32_t* bu = (const uint32_t*)bv;
            #pragma unroll
            for (int jt = 0; jt < 7; jt++) {
                uint32_t b0 = bu[jt * 2], b1 = bu[jt * 2 + 1];
                mma_tf32(d[jt], am0, b0, b1);
                mma_tf32(d[7 + jt], am1, b0, b1);
            }
        }
    }
    __half2 z2 = __float2half2_rn(0.f);
    #pragma unroll
    for (int mt = 0; mt < 2; mt++) {
        size_t r0 = rowbase + wid * 32 + mt * 16 + grp;
        __half* p0 = g_u + r0 * USTR;
        #pragma unroll
        for (int jt = 0; jt < 7; jt++) {
            int c0 = jt * 8 + 2 * qid;
            __half2 lo, hi;
            if (jt < 6 || qid == 0) {
                lo = __floats2half2_rn(d[mt * 7 + jt][0], d[mt * 7 + jt][1]);
                hi = __floats2half2_rn(d[mt * 7 + jt][2], d[mt * 7 + jt][3]);
            } else { lo = z2; hi = z2; }
            *(__half2*)(p0 + c0) = lo;
            *(__half2*)(p0 + 8 * USTR + c0) = hi;
        }
        int c0 = 56 + 2 * qid;
        *(__half2*)(p0 + c0) = z2;
        *(__half2*)(p0 + 8 * USTR + c0) = z2;
    }
}

// ---------------- SpMM: warp per (n, batch-quad); fp16 pre out ------------------
__global__ void __launch_bounds__(256) k_spmm() {
    int gw = blockIdx.x * 8 + (threadIdx.x >> 5);
    int lane = threadIdx.x & 31;
    int n = gw >> 5;          // 32 batch-quads per node
    int bq = gw & 31;
    const size_t P = (size_t)NNODES * USTR;
    const __half* ub0 = g_u + (size_t)(4 * bq) * P + 2 * lane;
    const __half* ub1 = ub0 + P;
    const __half* ub2 = ub0 + 2 * P;
    const __half* ub3 = ub0 + 3 * P;
    int e0 = g_csrptr[n], e1 = g_csrptr[n + 1];
    float sx0 = 0.f, sy0 = 0.f, sx1 = 0.f, sy1 = 0.f;
    float sx2 = 0.f, sy2 = 0.f, sx3 = 0.f, sy3 = 0.f;
    int e = e0;
    for (; e + 1 < e1; e += 2) {
        float2 m0 = g_epack[e], m1 = g_epack[e + 1];
        int o0 = __float_as_int(m0.y), o1 = __float_as_int(m1.y);
        float2 a0 = __half22float2(*(const __half2*)(ub0 + o0));
        float2 b0 = __half22float2(*(const __half2*)(ub1 + o0));
        float2 c0 = __half22float2(*(const __half2*)(ub2 + o0));
        float2 d0 = __half22float2(*(const __half2*)(ub3 + o0));
        float2 a1 = __half22float2(*(const __half2*)(ub0 + o1));
        float2 b1 = __half22float2(*(const __half2*)(ub1 + o1));
        float2 c1 = __half22float2(*(const __half2*)(ub2 + o1));
        float2 d1 = __half22float2(*(const __half2*)(ub3 + o1));
        sx0 += m0.x * a0.x + m1.x * a1.x;
        sy0 += m0.x * a0.y + m1.x * a1.y;
        sx1 += m0.x * b0.x + m1.x * b1.x;
        sy1 += m0.x * b0.y + m1.x * b1.y;
        sx2 += m0.x * c0.x + m1.x * c1.x;
        sy2 += m0.x * c0.y + m1.x * c1.y;
        sx3 += m0.x * d0.x + m1.x * d1.x;
        sy3 += m0.x * d0.y + m1.x * d1.y;
    }
    if (e < e1) {
        float2 m0 = g_epack[e];
        int o0 = __float_as_int(m0.y);
        float2 a0 = __half22float2(*(const __half2*)(ub0 + o0));
        float2 b0 = __half22float2(*(const __half2*)(ub1 + o0));
        float2 c0 = __half22float2(*(const __half2*)(ub2 + o0));
        float2 d0 = __half22float2(*(const __half2*)(ub3 + o0));
        sx0 += m0.x * a0.x; sy0 += m0.x * a0.y;
        sx1 += m0.x * b0.x; sy1 += m0.x * b0.y;
        sx2 += m0.x * c0.x; sy2 += m0.x * c0.y;
        sx3 += m0.x * d0.x; sy3 += m0.x * d0.y;
    }
    if (lane < 25) {
        float dv = g_dinv[n];
        float ws = dv * dv;
        int so = n * USTR;
        float2 fs0 = __half22float2(*(const __half2*)(ub0 + so));
        float2 fs1 = __half22float2(*(const __half2*)(ub1 + so));
        float2 fs2 = __half22float2(*(const __half2*)(ub2 + so));
        float2 fs3 = __half22float2(*(const __half2*)(ub3 + so));
        float2 cv = *(const float2*)(g_cvec + 2 * lane);
        const size_t Q = (size_t)NNODES * PSTR;
        __half* pp = g_pre + ((size_t)(4 * bq) * NNODES + n) * PSTR + 2 * lane;
        *(__half2*)pp =
            __floats2half2_rn(sx0 + ws * fs0.x + cv.x, sy0 + ws * fs0.y + cv.y);
        *(__half2*)(pp + Q) =
            __floats2half2_rn(sx1 + ws * fs1.x + cv.x, sy1 + ws * fs1.y + cv.y);
        *(__half2*)(pp + 2 * Q) =
            __floats2half2_rn(sx2 + ws * fs2.x + cv.x, sy2 + ws * fs2.y + cv.y);
        *(__half2*)(pp + 3 * Q) =
            __floats2half2_rn(sx3 + ws * fs3.x + cv.x, sy3 + ws * fs3.y + cv.y);
    }
}

// ---------------- RNN: warp per node, lane owns cols {2l,2l+1}, fp16 pre --------
__global__ void __launch_bounds__(128) k_rnn(const float* __restrict__ Whh,
                                             const float* __restrict__ bhh,
                                             const float* __restrict__ h0,
                                             float* __restrict__ out) {
    int w = blockIdx.x * 4 + (threadIdx.x >> 5);
    int lane = threadIdx.x & 31;
    if (w >= NNODES) return;
    __shared__ __align__(16) float hsm[4][2][52];
    float* hc = hsm[threadIdx.x >> 5][0];
    float* hn = hsm[threadIdx.x >> 5][1];
    bool act = lane < 25;
    int c0 = act ? 2 * lane : 0;
    int c1 = act ? 2 * lane + 1 : 1;
    // pack W_hh rows into f32x2 pairs (26 per output col; pair 25 = 0)
    unsigned long long w0p[26], w1p[26];
    #pragma unroll
    for (int k = 0; k < 25; k++) {
        w0p[k] = pk2(Whh[c0 * HS + 2 * k], Whh[c0 * HS + 2 * k + 1]);
        w1p[k] = pk2(Whh[c1 * HS + 2 * k], Whh[c1 * HS + 2 * k + 1]);
    }
    unsigned long long zz = pk2(0.f, 0.f);
    w0p[25] = zz; w1p[25] = zz;
    float b0 = bhh[c0];
    float b1 = bhh[c1];
    if (act)
        *(float2*)&hc[2 * lane] = *(const float2*)&h0[(size_t)w * HS + 2 * lane];
    if (lane == 25) { hc[50] = 0.f; hc[51] = 0.f; hn[50] = 0.f; hn[51] = 0.f; }
    __syncwarp();
    const __half* prew = g_pre + (size_t)w * PSTR + 2 * lane;
    float* outw = out + (size_t)w * HS + 2 * lane;
    const size_t pstr = (size_t)NNODES * PSTR;
    const size_t ostr = (size_t)NNODES * HS;
    // prefetch distance 4 (half2 packed)
    uint32_t pf[4];
    #pragma unroll
    for (int j = 0; j < 4; j++) pf[j] = *(const uint32_t*)(prew + j * pstr);
    prew += 4 * pstr;
    #pragma unroll 1
    for (int t = 0; t < NB; t += 4) {
        #pragma unroll
        for (int j = 0; j < 4; j++) {
            float2 pv = __half22float2(*(__half2*)&pf[j]);
            float a0 = pv.x + b0;
            float a1 = pv.y + b1;
            pf[j] = *(const uint32_t*)(prew + j * pstr);
            unsigned long long acc0 = zz, acc1 = zz, acc2 = zz, acc3 = zz;
            #pragma unroll
            for (int kk = 0; kk < 13; kk++) {
                ulonglong2 hp = *(const ulonglong2*)&hc[kk * 4];
                acc0 = fma2(hp.x, w0p[2 * kk], acc0);
                acc1 = fma2(hp.y, w0p[2 * kk + 1], acc1);
                acc2 = fma2(hp.x, w1p[2 * kk], acc2);
                acc3 = fma2(hp.y, w1p[2 * kk + 1], acc3);
            }
            float2 u0 = upk2(acc0), u1 = upk2(acc1);
            float2 u2 = upk2(acc2), u3 = upk2(acc3);
            float t0 = fast_tanh(a0 + (u0.x + u0.y) + (u1.x + u1.y));
            float t1 = fast_tanh(a1 + (u2.x + u2.y) + (u3.x + u3.y));
            if (act) *(float2*)&hn[2 * lane] = make_float2(t0, t1);
            __syncwarp();
            float* tmp = hc; hc = hn; hn = tmp;
            if (act) *(float2*)outw = make_float2(t0, t1);
            outw += ostr;
        }
        prew += 4 * pstr;
    }
}

// ---------------- launch ----------------
extern "C" void kernel_launch(void* const* d_in, const int* in_sizes, int n_in,
                              void* d_out, int out_size) {
    const float* x    = (const float*)d_in[0];
    const void*  eidx = d_in[1];
    const float* ew   = (const float*)d_in[2];
    const float* W    = (const float*)d_in[3];
    const float* b    = (const float*)d_in[4];
    const float* W_ih = (const float*)d_in[5];
    const float* W_hh = (const float*)d_in[6];
    const float* b_ih = (const float*)d_in[7];
    const float* b_hh = (const float*)d_in[8];
    const float* h0   = (const float*)d_in[9];
    float* out = (float*)d_out;

    k_setup<<<(2 * NEDGES + 255) / 256, 256>>>(eidx, W, b, W_ih, b_ih);  // 0
    k_scan<<<1, 1024>>>(0);                                  // 1
    k_edges<<<(NEDGES + 255) / 256, 256>>>(eidx, ew);        // 2
    k_gemm<<<NNODES, 128>>>(x);                              // 3  <- profiled (control)
    k_scan<<<1, 1024>>>(1);                                  // 4
    k_fill<<<(NEDGES + 255) / 256, 256>>>(ew);               // 5
    k_spmm<<<(NB * NNODES / 4) / 8, 256>>>();                // 6
    k_rnn<<<(NNODES + 3) / 4, 128>>>(W_hh, b_hh, h0, out);   // 7
}

// round 17
// speedup vs baseline: 1.4868x; 1.0336x over previous
#include <cuda_runtime.h>
#include <cuda_fp16.h>
#include <math.h>
#include <stdint.h>

#define NNODES 3070
#define NFEAT 128
#define NOUT 64
#define HS 50
#define HSP 52           // cvec padding only
#define USTR 64          // fp16 u row: 64 halves = 128B (one cache line)
#define PSTR 64          // fp16 pre row: 64 halves = 128B
#define NEDGES 49120
#define NB 128
#define NROWS (NB * NNODES)

// ---------------- device scratch (static, no allocations) ----------------
__device__ int   g_is64;
__device__ int   g_present[NNODES];   // idempotent marks; never re-zeroed
__device__ int   g_rank[NNODES];
__device__ float g_deg[NNODES];
__device__ float g_dinv[NNODES];
__device__ int   g_counts[NNODES];
__device__ int   g_csrptr[NNODES + 1];
__device__ int   g_cursor[NNODES];
__device__ int   g_esrc[NEDGES];
__device__ int   g_edst[NEDGES];
__device__ __align__(8) float2 g_epack[NEDGES];  // (norm_w, src*USTR as int bits)
// B fragments in mma order: [s(16)][jp(4)][lane(32)][slot(4)] = 32KB
__device__ __align__(16) float g_Bfrag[16 * 4 * 32 * 4];
__device__ __align__(16) float g_cvec[HSP];
__device__ __align__(256) __half g_u[(size_t)NROWS * USTR];
// fp16 pre, padded by FOUR batch-rows for branch-free distance-4 prefetch
__device__ __align__(256) __half g_pre[(size_t)(NROWS + 4 * NNODES) * PSTR];

__device__ __forceinline__ uint32_t to_tf32(float f) {
    uint32_t r;
    asm("cvt.rna.tf32.f32 %0, %1;" : "=r"(r) : "f"(f));
    return r;
}
__device__ __forceinline__ void mma_tf32(float* d, const uint32_t* a,
                                         uint32_t b0, uint32_t b1) {
    asm volatile(
        "mma.sync.aligned.m16n8k8.row.col.f32.tf32.tf32.f32 "
        "{%0,%1,%2,%3}, {%4,%5,%6,%7}, {%8,%9}, {%0,%1,%2,%3};"
        : "+f"(d[0]), "+f"(d[1]), "+f"(d[2]), "+f"(d[3])
        : "r"(a[0]), "r"(a[1]), "r"(a[2]), "r"(a[3]), "r"(b0), "r"(b1));
}
// accurate fast tanh: ex2/rcp approx are ~2^-23 rel err -> ~1e-6 overall
__device__ __forceinline__ float fast_tanh(float x) {
    float e;
    asm("ex2.approx.f32 %0, %1;" : "=f"(e) : "f"(x * 2.8853900817779268f));
    float r;
    asm("rcp.approx.f32 %0, %1;" : "=f"(r) : "f"(e + 1.0f));
    return fmaf(-2.0f, r, 1.0f);
}
// packed f32x2 fma (Blackwell FFMA2, base sm_100+ feature)
__device__ __forceinline__ unsigned long long fma2(unsigned long long a,
                                                   unsigned long long b,
                                                   unsigned long long c) {
    unsigned long long d;
    asm("fma.rn.f32x2 %0, %1, %2, %3;" : "=l"(d) : "l"(a), "l"(b), "l"(c));
    return d;
}
__device__ __forceinline__ unsigned long long pk2(float x, float y) {
    unsigned long long r;
    asm("mov.b64 %0, {%1, %2};" : "=l"(r) : "f"(x), "f"(y));
    return r;
}
__device__ __forceinline__ float2 upk2(unsigned long long v) {
    float2 r;
    asm("mov.b64 {%0, %1}, %2;" : "=f"(r.x), "=f"(r.y) : "l"(v));
    return r;
}

__device__ __forceinline__ int load_eid(const void* eidx, int i, int is64) {
    if (is64) return (int)((const long long*)eidx)[i];
    return ((const int*)eidx)[i];
}

// ---------------- setupB: B fragments + cvec (gemm branch) ----------------------
__global__ void k_setupB(const float* __restrict__ W, const float* __restrict__ b,
                         const float* __restrict__ W_ih,
                         const float* __restrict__ b_ih) {
    int i = blockIdx.x * 256 + threadIdx.x;
    if (i < 128 * 64) {
        int k = i >> 6, c = i & 63;
        float v = 0.f;
        if (c < HS) {
            float s = 0.f;
            #pragma unroll 8
            for (int o = 0; o < NOUT; o++) s += W[k * NOUT + o] * W_ih[c * NOUT + o];
            v = __uint_as_float(to_tf32(s));
        }
        int t16 = k >> 4, j = k & 15, q = j >> 2, r = j & 3;
        int sct = 2 * t16 + (r >> 1);
        int bidx = r & 1;
        int klo = q;
        int jcol = c >> 3, nr = c & 7, jp = jcol >> 1, jodd = jcol & 1;
        int lane = nr * 4 + klo;
        g_Bfrag[(((sct * 4 + jp) * 32 + lane) << 2) + jodd * 2 + bidx] = v;
    }
    int ci = i - 128 * 64;
    if (ci >= 0 && ci < HS) {
        float s = b_ih[ci];
        #pragma unroll 8
        for (int o = 0; o < NOUT; o++) s += b[o] * W_ih[ci * NOUT + o];
        g_cvec[ci] = s;
    }
    if (ci == HS) { g_cvec[50] = 0.f; g_cvec[51] = 0.f; }
}

// ---------------- mark: dtype detect + presence marks + init --------------------
__global__ void k_mark(const void* eidx) {
    __shared__ int s_is64;
    int t = threadIdx.x;
    if (t < 32) {
        int val = (t < 8) ? ((const int*)eidx)[2 * t + 1] : 0;
        int any = __any_sync(0xffffffffu, val != 0);
        if (t == 0) s_is64 = !any;
    }
    __syncthreads();
    int is64 = s_is64;
    int i = blockIdx.x * 256 + t;
    if (i == 0) g_is64 = is64;
    if (i < 2 * NEDGES) g_present[load_eid(eidx, i, is64)] = 1;
    if (i < NNODES) { g_deg[i] = 1.0f; g_counts[i] = 0; }
}

// ---------------- single-block exclusive scans ----------------
__global__ void k_scan(int mode) {
    __shared__ int sa[1024], sb[1024];
    int t = threadIdx.x;
    int base = t * 3;
    const int* in = mode ? g_counts : g_present;
    int v0 = (base     < NNODES) ? in[base]     : 0;
    int v1 = (base + 1 < NNODES) ? in[base + 1] : 0;
    int v2 = (base + 2 < NNODES) ? in[base + 2] : 0;
    int s = v0 + v1 + v2;
    sa[t] = s;
    __syncthreads();
    int* src = sa; int* dst = sb;
    for (int off = 1; off < 1024; off <<= 1) {
        int val = src[t];
        if (t >= off) val += src[t - off];
        dst[t] = val;
        __syncthreads();
        int* tmp = src; src = dst; dst = tmp;
    }
    int incl = src[t];
    int excl = incl - s;
    if (mode == 0) {
        if (base     < NNODES) g_rank[base]     = excl;
        if (base + 1 < NNODES) g_rank[base + 1] = excl + v0;
        if (base + 2 < NNODES) g_rank[base + 2] = excl + v0 + v1;
    } else {
        if (base < NNODES) {
            g_csrptr[base] = excl; g_cursor[base] = excl;
            g_dinv[base] = rsqrtf(g_deg[base]);
        }
        if (base + 1 < NNODES) {
            g_csrptr[base + 1] = excl + v0; g_cursor[base + 1] = excl + v0;
            g_dinv[base + 1] = rsqrtf(g_deg[base + 1]);
        }
        if (base + 2 < NNODES) {
            g_csrptr[base + 2] = excl + v0 + v1; g_cursor[base + 2] = excl + v0 + v1;
            g_dinv[base + 2] = rsqrtf(g_deg[base + 2]);
        }
        if (t == 1023) g_csrptr[NNODES] = incl;
    }
}

// ---------------- remap edges + degree/counts ----------------
__global__ void k_edges(const void* eidx, const float* __restrict__ ew) {
    int e = blockIdx.x * 256 + threadIdx.x;
    if (e >= NEDGES) return;
    int is64 = g_is64;
    int sid = load_eid(eidx, e, is64);
    int did = load_eid(eidx, NEDGES + e, is64);
    int s = g_rank[sid], d = g_rank[did];
    g_esrc[e] = s;
    g_edst[e] = d;
    atomicAdd(&g_deg[d], ew[e]);
    atomicAdd(&g_counts[d], 1);
}

// ---------------- fill CSR (by dst): packed (w, src*USTR) ----------------
__global__ void k_fill(const float* __restrict__ ew) {
    int e = blockIdx.x * 256 + threadIdx.x;
    if (e >= NEDGES) return;
    int d = g_edst[e], s = g_esrc[e];
    int pos = atomicAdd(&g_cursor[d], 1);
    g_epack[pos] = make_float2(g_dinv[s] * ew[e] * g_dinv[d],
                               __int_as_float(s * USTR));
}

// ---------------- GEMM: u = x @ M via mma.sync tf32 m16n8k8, fp16 out -----------
__global__ void __launch_bounds__(128) k_gemm(const float* __restrict__ x) {
    __shared__ __align__(16) float4 Bs[16 * 4 * 32];
    int tid = threadIdx.x, wid = tid >> 5, lane = tid & 31;
    {
        const float4* s = (const float4*)g_Bfrag;
        #pragma unroll
        for (int i = 0; i < 16; i++) Bs[tid + 128 * i] = s[tid + 128 * i];
    }
    size_t rowbase = (size_t)blockIdx.x * 128;
    int grp = lane >> 2, qid = lane & 3;
    const float* px = x + (rowbase + wid * 32 + grp) * NFEAT + 4 * qid;
    __syncthreads();

    float d[14][4];
    #pragma unroll
    for (int i = 0; i < 14; i++)
        #pragma unroll
        for (int j = 0; j < 4; j++) d[i][j] = 0.f;

    #pragma unroll
    for (int t = 0; t < 8; t++) {
        float4 v0 = *(const float4*)(px + 16 * t);
        float4 v1 = *(const float4*)(px + 8 * NFEAT + 16 * t);
        float4 v2 = *(const float4*)(px + 16 * NFEAT + 16 * t);
        float4 v3 = *(const float4*)(px + 24 * NFEAT + 16 * t);
        #pragma unroll
        for (int ss = 0; ss < 2; ss++) {
            int s = 2 * t + ss;
            uint32_t am0[4], am1[4];
            if (ss == 0) {
                am0[0] = to_tf32(v0.x); am0[1] = to_tf32(v1.x);
                am0[2] = to_tf32(v0.y); am0[3] = to_tf32(v1.y);
                am1[0] = to_tf32(v2.x); am1[1] = to_tf32(v3.x);
                am1[2] = to_tf32(v2.y); am1[3] = to_tf32(v3.y);
            } else {
                am0[0] = to_tf32(v0.z); am0[1] = to_tf32(v1.z);
                am0[2] = to_tf32(v0.w); am0[3] = to_tf32(v1.w);
                am1[0] = to_tf32(v2.z); am1[1] = to_tf32(v3.z);
                am1[2] = to_tf32(v2.w); am1[3] = to_tf32(v3.w);
            }
            float4 bv[4];
            #pragma unroll
            for (int jp = 0; jp < 4; jp++) bv[jp] = Bs[(s * 4 + jp) * 32 + lane];
            const uint32_t* bu = (const uint32_t*)bv;
            #pragma unroll
            for (int jt = 0; jt < 7; jt++) {
                uint32_t b0 = bu[jt * 2], b1 = bu[jt * 2 + 1];
                mma_tf32(d[jt], am0, b0, b1);
                mma_tf32(d[7 + jt], am1, b0, b1);
            }
        }
    }
    __half2 z2 = __float2half2_rn(0.f);
    #pragma unroll
    for (int mt = 0; mt < 2; mt++) {
        size_t r0 = rowbase + wid * 32 + mt * 16 + grp;
        __half* p0 = g_u + r0 * USTR;
        #pragma unroll
        for (int jt = 0; jt < 7; jt++) {
            int c0 = jt * 8 + 2 * qid;
            __half2 lo, hi;
            if (jt < 6 || qid == 0) {
                lo = __floats2half2_rn(d[mt * 7 + jt][0], d[mt * 7 + jt][1]);
                hi = __floats2half2_rn(d[mt * 7 + jt][2], d[mt * 7 + jt][3]);
            } else { lo = z2; hi = z2; }
            *(__half2*)(p0 + c0) = lo;
            *(__half2*)(p0 + 8 * USTR + c0) = hi;
        }
        int c0 = 56 + 2 * qid;
        *(__half2*)(p0 + c0) = z2;
        *(__half2*)(p0 + 8 * USTR + c0) = z2;
    }
}

// ---------------- SpMM: warp per (n, batch-quad); fp16 pre out ------------------
__global__ void __launch_bounds__(256) k_spmm() {
    int gw = blockIdx.x * 8 + (threadIdx.x >> 5);
    int lane = threadIdx.x & 31;
    int n = gw >> 5;          // 32 batch-quads per node
    int bq = gw & 31;
    const size_t P = (size_t)NNODES * USTR;
    const __half* ub0 = g_u + (size_t)(4 * bq) * P + 2 * lane;
    const __half* ub1 = ub0 + P;
    const __half* ub2 = ub0 + 2 * P;
    const __half* ub3 = ub0 + 3 * P;
    int e0 = g_csrptr[n], e1 = g_csrptr[n + 1];
    float sx0 = 0.f, sy0 = 0.f, sx1 = 0.f, sy1 = 0.f;
    float sx2 = 0.f, sy2 = 0.f, sx3 = 0.f, sy3 = 0.f;
    int e = e0;
    for (; e + 1 < e1; e += 2) {
        float2 m0 = g_epack[e], m1 = g_epack[e + 1];
        int o0 = __float_as_int(m0.y), o1 = __float_as_int(m1.y);
        float2 a0 = __half22float2(*(const __half2*)(ub0 + o0));
        float2 b0 = __half22float2(*(const __half2*)(ub1 + o0));
        float2 c0 = __half22float2(*(const __half2*)(ub2 + o0));
        float2 d0 = __half22float2(*(const __half2*)(ub3 + o0));
        float2 a1 = __half22float2(*(const __half2*)(ub0 + o1));
        float2 b1 = __half22float2(*(const __half2*)(ub1 + o1));
        float2 c1 = __half22float2(*(const __half2*)(ub2 + o1));
        float2 d1 = __half22float2(*(const __half2*)(ub3 + o1));
        sx0 += m0.x * a0.x + m1.x * a1.x;
        sy0 += m0.x * a0.y + m1.x * a1.y;
        sx1 += m0.x * b0.x + m1.x * b1.x;
        sy1 += m0.x * b0.y + m1.x * b1.y;
        sx2 += m0.x * c0.x + m1.x * c1.x;
        sy2 += m0.x * c0.y + m1.x * c1.y;
        sx3 += m0.x * d0.x + m1.x * d1.x;
        sy3 += m0.x * d0.y + m1.x * d1.y;
    }
    if (e < e1) {
        float2 m0 = g_epack[e];
        int o0 = __float_as_int(m0.y);
        float2 a0 = __half22float2(*(const __half2*)(ub0 + o0));
        float2 b0 = __half22float2(*(const __half2*)(ub1 + o0));
        float2 c0 = __half22float2(*(const __half2*)(ub2 + o0));
        float2 d0 = __half22float2(*(const __half2*)(ub3 + o0));
        sx0 += m0.x * a0.x; sy0 += m0.x * a0.y;
        sx1 += m0.x * b0.x; sy1 += m0.x * b0.y;
        sx2 += m0.x * c0.x; sy2 += m0.x * c0.y;
        sx3 += m0.x * d0.x; sy3 += m0.x * d0.y;
    }
    if (lane < 25) {
        float dv = g_dinv[n];
        float ws = dv * dv;
        int so = n * USTR;
        float2 fs0 = __half22float2(*(const __half2*)(ub0 + so));
        float2 fs1 = __half22float2(*(const __half2*)(ub1 + so));
        float2 fs2 = __half22float2(*(const __half2*)(ub2 + so));
        float2 fs3 = __half22float2(*(const __half2*)(ub3 + so));
        float2 cv = *(const float2*)(g_cvec + 2 * lane);
        const size_t Q = (size_t)NNODES * PSTR;
        __half* pp = g_pre + ((size_t)(4 * bq) * NNODES + n) * PSTR + 2 * lane;
        *(__half2*)pp =
            __floats2half2_rn(sx0 + ws * fs0.x + cv.x, sy0 + ws * fs0.y + cv.y);
        *(__half2*)(pp + Q) =
            __floats2half2_rn(sx1 + ws * fs1.x + cv.x, sy1 + ws * fs1.y + cv.y);
        *(__half2*)(pp + 2 * Q) =
            __floats2half2_rn(sx2 + ws * fs2.x + cv.x, sy2 + ws * fs2.y + cv.y);
        *(__half2*)(pp + 3 * Q) =
            __floats2half2_rn(sx3 + ws * fs3.x + cv.x, sy3 + ws * fs3.y + cv.y);
    }
}

// ---------------- RNN: warp per node, lane owns cols {2l,2l+1}, fp16 pre --------
__global__ void __launch_bounds__(128) k_rnn(const float* __restrict__ Whh,
                                             const float* __restrict__ bhh,
                                             const float* __restrict__ h0,
                                             float* __restrict__ out) {
    int w = blockIdx.x * 4 + (threadIdx.x >> 5);
    int lane = threadIdx.x & 31;
    if (w >= NNODES) return;
    __shared__ __align__(16) float hsm[4][2][52];
    float* hc = hsm[threadIdx.x >> 5][0];
    float* hn = hsm[threadIdx.x >> 5][1];
    bool act = lane < 25;
    int c0 = act ? 2 * lane : 0;
    int c1 = act ? 2 * lane + 1 : 1;
    // pack W_hh rows into f32x2 pairs (26 per output col; pair 25 = 0)
    unsigned long long w0p[26], w1p[26];
    #pragma unroll
    for (int k = 0; k < 25; k++) {
        w0p[k] = pk2(Whh[c0 * HS + 2 * k], Whh[c0 * HS + 2 * k + 1]);
        w1p[k] = pk2(Whh[c1 * HS + 2 * k], Whh[c1 * HS + 2 * k + 1]);
    }
    unsigned long long zz = pk2(0.f, 0.f);
    w0p[25] = zz; w1p[25] = zz;
    float b0 = bhh[c0];
    float b1 = bhh[c1];
    if (act)
        *(float2*)&hc[2 * lane] = *(const float2*)&h0[(size_t)w * HS + 2 * lane];
    if (lane == 25) { hc[50] = 0.f; hc[51] = 0.f; hn[50] = 0.f; hn[51] = 0.f; }
    __syncwarp();
    const __half* prew = g_pre + (size_t)w * PSTR + 2 * lane;
    float* outw = out + (size_t)w * HS + 2 * lane;
    const size_t pstr = (size_t)NNODES * PSTR;
    const size_t ostr = (size_t)NNODES * HS;
    // prefetch distance 4 (half2 packed)
    uint32_t pf[4];
    #pragma unroll
    for (int j = 0; j < 4; j++) pf[j] = *(const uint32_t*)(prew + j * pstr);
    prew += 4 * pstr;
    #pragma unroll 1
    for (int t = 0; t < NB; t += 4) {
        #pragma unroll
        for (int j = 0; j < 4; j++) {
            float2 pv = __half22float2(*(__half2*)&pf[j]);
            float a0 = pv.x + b0;
            float a1 = pv.y + b1;
            pf[j] = *(const uint32_t*)(prew + j * pstr);
            unsigned long long acc0 = zz, acc1 = zz, acc2 = zz, acc3 = zz;
            #pragma unroll
            for (int kk = 0; kk < 13; kk++) {
                ulonglong2 hp = *(const ulonglong2*)&hc[kk * 4];
                acc0 = fma2(hp.x, w0p[2 * kk], acc0);
                acc1 = fma2(hp.y, w0p[2 * kk + 1], acc1);
                acc2 = fma2(hp.x, w1p[2 * kk], acc2);
                acc3 = fma2(hp.y, w1p[2 * kk + 1], acc3);
            }
            float2 u0 = upk2(acc0), u1 = upk2(acc1);
            float2 u2 = upk2(acc2), u3 = upk2(acc3);
            float t0 = fast_tanh(a0 + (u0.x + u0.y) + (u1.x + u1.y));
            float t1 = fast_tanh(a1 + (u2.x + u2.y) + (u3.x + u3.y));
            if (act) *(float2*)&hn[2 * lane] = make_float2(t0, t1);
            __syncwarp();
            float* tmp = hc; hc = hn; hn = tmp;
            if (act) *(float2*)outw = make_float2(t0, t1);
            outw += ostr;
        }
        prew += 4 * pstr;
    }
}

// ---------------- launch: forked graph (prep branch ∥ gemm branch) --------------
extern "C" void kernel_launch(void* const* d_in, const int* in_sizes, int n_in,
                              void* d_out, int out_size) {
    const float* x    = (const float*)d_in[0];
    const void*  eidx = d_in[1];
    const float* ew   = (const float*)d_in[2];
    const float* W    = (const float*)d_in[3];
    const float* b    = (const float*)d_in[4];
    const float* W_ih = (const float*)d_in[5];
    const float* W_hh = (const float*)d_in[6];
    const float* b_ih = (const float*)d_in[7];
    const float* b_hh = (const float*)d_in[8];
    const float* h0   = (const float*)d_in[9];
    float* out = (float*)d_out;

    // lazily-created side stream + events (host resources; work is unchanged
    // and deterministic on every call)
    static cudaStream_t s2 = nullptr;
    static cudaEvent_t evRoot = nullptr, evJoin = nullptr;
    if (s2 == nullptr) {
        cudaStreamCreateWithFlags(&s2, cudaStreamNonBlocking);
        cudaEventCreateWithFlags(&evRoot, cudaEventDisableTiming);
        cudaEventCreateWithFlags(&evJoin, cudaEventDisableTiming);
    }

    // fork
    cudaEventRecord(evRoot, 0);
    cudaStreamWaitEvent(s2, evRoot, 0);
    // branch A (s2): weight fold + GEMM (independent of graph prep)
    k_setupB<<<33, 256, 0, s2>>>(W, b, W_ih, b_ih);
    k_gemm<<<NNODES, 128, 0, s2>>>(x);
    cudaEventRecord(evJoin, s2);
    // branch B (capture stream): graph preprocessing chain
    k_mark<<<(2 * NEDGES + 255) / 256, 256>>>(eidx);
    k_scan<<<1, 1024>>>(0);
    k_edges<<<(NEDGES + 255) / 256, 256>>>(eidx, ew);
    k_scan<<<1, 1024>>>(1);
    k_fill<<<(NEDGES + 255) / 256, 256>>>(ew);
    // join, then consumers
    cudaStreamWaitEvent(0, evJoin, 0);
    k_spmm<<<(NB * NNODES / 4) / 8, 256>>>();
    k_rnn<<<(NNODES + 3) / 4, 128>>>(W_hh, b_hh, h0, out);
}